// round 1
// baseline (speedup 1.0000x reference)
#include <cuda_runtime.h>
#include <cuda_bf16.h>

// ---------------- problem constants ----------------
#define BATCH 4
#define LTOK 513          // N_PATCH + 1
#define NPATCH 512
#define ROWS (BATCH*LTOK) // 2052
#define DM 768
#define DI 1536
#define DX 3072           // 2*DI
#define DTR 48
#define DST 16
#define DBLN 80           // DTR + 2*DST
#define DEPTH 24
#define PKK 256           // 16*16 patch

typedef unsigned long long u64;
typedef long long i64;

// ---------------- scratch (static device memory; no allocation) ----------------
__device__ __align__(256) float g_xp [BATCH*NPATCH*PKK];
__device__ __align__(256) float g_h  [ROWS*DM];
__device__ __align__(256) float g_res[ROWS*DM];
__device__ __align__(256) float g_xn [ROWS*DM];
__device__ __align__(256) float g_xz [ROWS*DX];
__device__ __align__(256) float g_c  [2*ROWS*DI];
__device__ __align__(256) float g_dbl[2*ROWS*DBLN];
__device__ __align__(256) float g_dt [2*ROWS*DI];
__device__ __align__(256) float g_y  [2*ROWS*DI];
__device__ __align__(256) float g_yc [ROWS*DI];

// ---------------- f32x2 packed-FMA helpers (sm_100+) ----------------
__device__ __forceinline__ u64 pk2(float x, float y){
    u64 r; asm("mov.b64 %0,{%1,%2};" : "=l"(r) : "f"(x), "f"(y)); return r;
}
__device__ __forceinline__ void upk2(u64 v, float &x, float &y){
    asm("mov.b64 {%0,%1},%2;" : "=f"(x), "=f"(y) : "l"(v));
}
__device__ __forceinline__ u64 ffma2(u64 a, u64 b, u64 c){
    u64 d; asm("fma.rn.f32x2 %0,%1,%2,%3;" : "=l"(d) : "l"(a), "l"(b), "l"(c)); return d;
}

__device__ __forceinline__ float softplusf(float x){
    return x > 20.f ? x : log1pf(__expf(x));
}
__device__ __forceinline__ float siluf(float x){
    return x / (1.f + __expf(-x));
}

// ---------------- generic SGEMM: C[M,N] = A[M,K] * B[N,K]^T  (+ epilogues) ----------------
// 128x128 block tile, BK=16, 8x8 per thread, 256 threads, packed f32x2 FMA.
// Requires: K % 16 == 0, lda/ldb multiples of 4, bases 16B-aligned.
#define GBM 128
#define GBN 128
#define GBK 16
#define GTM 8
#define GTN 8
#define EPI_PLAIN 0
#define EPI_PATCH 1
#define EPI_SOFTPLUS 2

__global__ void __launch_bounds__(256,2) sgemm_k(
    const float* __restrict__ A, const float* __restrict__ Bw, float* __restrict__ C,
    int M, int N, int K, int lda, int ldb, int ldc,
    i64 bsA, i64 bsB, i64 bsC,
    int mode, const float* __restrict__ bias, i64 bsBias,
    const float* __restrict__ pos)
{
    A  += (i64)blockIdx.z * bsA;
    Bw += (i64)blockIdx.z * bsB;
    C  += (i64)blockIdx.z * bsC;
    if (bias) bias += (i64)blockIdx.z * bsBias;

    __shared__ float As[GBK][GBM+4];
    __shared__ float Bs[GBK][GBN+4];

    const int tid = threadIdx.x;
    const int m0 = blockIdx.y * GBM;
    const int n0 = blockIdx.x * GBN;
    const int lr = tid >> 2;            // 0..63
    const int lk = (tid & 3) * 4;       // 0,4,8,12
    const int tr = (tid >> 4) * GTM;    // 0..120
    const int tc = (tid & 15) * GTN;    // 0..120

    u64 acc[GTM][GTN/2];
    #pragma unroll
    for (int i=0;i<GTM;i++)
        #pragma unroll
        for (int j=0;j<GTN/2;j++) acc[i][j] = 0ULL;

    for (int k0 = 0; k0 < K; k0 += GBK) {
        #pragma unroll
        for (int hh=0; hh<2; hh++) {
            int r = lr + hh*64;
            int am = m0 + r;
            float4 av = make_float4(0.f,0.f,0.f,0.f);
            if (am < M) av = *reinterpret_cast<const float4*>(A + (i64)am*lda + (k0+lk));
            As[lk+0][r]=av.x; As[lk+1][r]=av.y; As[lk+2][r]=av.z; As[lk+3][r]=av.w;
            int bn = n0 + r;
            float4 bv = make_float4(0.f,0.f,0.f,0.f);
            if (bn < N) bv = *reinterpret_cast<const float4*>(Bw + (i64)bn*ldb + (k0+lk));
            Bs[lk+0][r]=bv.x; Bs[lk+1][r]=bv.y; Bs[lk+2][r]=bv.z; Bs[lk+3][r]=bv.w;
        }
        __syncthreads();
        #pragma unroll
        for (int k=0;k<GBK;k++) {
            float a[GTM];
            *reinterpret_cast<float4*>(&a[0]) = *reinterpret_cast<const float4*>(&As[k][tr]);
            *reinterpret_cast<float4*>(&a[4]) = *reinterpret_cast<const float4*>(&As[k][tr+4]);
            u64 bfrag[GTN/2];
            const u64* bp = reinterpret_cast<const u64*>(&Bs[k][tc]);
            bfrag[0]=bp[0]; bfrag[1]=bp[1]; bfrag[2]=bp[2]; bfrag[3]=bp[3];
            #pragma unroll
            for (int i=0;i<GTM;i++) {
                u64 a2 = pk2(a[i], a[i]);
                #pragma unroll
                for (int j=0;j<GTN/2;j++)
                    acc[i][j] = ffma2(a2, bfrag[j], acc[i][j]);
            }
        }
        __syncthreads();
    }

    #pragma unroll
    for (int i=0;i<GTM;i++) {
        int m = m0 + tr + i;
        if (m >= M) continue;
        #pragma unroll
        for (int j=0;j<GTN/2;j++) {
            int n = n0 + tc + 2*j;
            if (n >= N) continue;
            float x, y;
            upk2(acc[i][j], x, y);
            if (mode == EPI_PLAIN) {
                if (n+1 < N) *reinterpret_cast<float2*>(C + (i64)m*ldc + n) = make_float2(x,y);
                else C[(i64)m*ldc + n] = x;
            } else if (mode == EPI_SOFTPLUS) {
                x = softplusf(x + bias[n]);
                if (n+1 < N) {
                    y = softplusf(y + bias[n+1]);
                    *reinterpret_cast<float2*>(C + (i64)m*ldc + n) = make_float2(x,y);
                } else C[(i64)m*ldc + n] = x;
            } else { // EPI_PATCH: remap patch rows -> token rows (skip CLS), add patch_b + pos_embed
                int p = m & (NPATCH-1);
                int row = (m >> 9)*LTOK + p + 1;
                float2 v;
                v.x = x + bias[n]   + pos[(i64)(p+1)*DM + n];
                v.y = y + bias[n+1] + pos[(i64)(p+1)*DM + n + 1];
                *reinterpret_cast<float2*>(C + (i64)row*ldc + n) = v;
            }
        }
    }
}

// ---------------- patch gather: xp[b, f*64+t, i*16+j] = x[b, f*16+i, t*16+j] ----------------
__global__ void gather_xp_k(const float* __restrict__ x, float* __restrict__ xp){
    i64 idx = (i64)blockIdx.x*256 + threadIdx.x;
    if (idx >= (i64)BATCH*NPATCH*PKK) return;
    int k = (int)(idx & 255);
    int p = (int)((idx >> 8) & 511);
    int b = (int)(idx >> 17);
    int i = k >> 4, j = k & 15;
    int f = p >> 6, t = p & 63;
    xp[idx] = x[(i64)(b*128 + f*16 + i)*1024 + t*16 + j];
}

// ---------------- cls row fill: h[b,0,:] = cls + pos[0,:] ----------------
__global__ void cls_fill_k(const float* __restrict__ cls, const float* __restrict__ pos,
                           float* __restrict__ h){
    int idx = blockIdx.x*256 + threadIdx.x;
    if (idx >= BATCH*DM) return;
    int b = idx / DM, d = idx % DM;
    h[(i64)(b*LTOK)*DM + d] = cls[d] + pos[d];
}

// ---------------- res = (first ? h : res + h); xn = rms_norm(res)*lw ----------------
__global__ void __launch_bounds__(256) addrms_k(
    float* __restrict__ res, const float* __restrict__ h, float* __restrict__ xn,
    const float* __restrict__ lw, int first)
{
    int r = blockIdx.x;
    const float* hr = h + (i64)r*DM;
    float* rr = res + (i64)r*DM;
    float* xr = xn + (i64)r*DM;
    int tid = threadIdx.x;
    float v[3]; float ss = 0.f;
    #pragma unroll
    for (int i=0;i<3;i++){
        int d = tid + i*256;
        float t = first ? hr[d] : (rr[d] + hr[d]);
        v[i] = t; rr[d] = t; ss += t*t;
    }
    __shared__ float red[256];
    red[tid] = ss; __syncthreads();
    for (int s=128; s>0; s>>=1){ if (tid < s) red[tid] += red[tid+s]; __syncthreads(); }
    float scale = rsqrtf(red[0]/(float)DM + 1e-5f);
    #pragma unroll
    for (int i=0;i<3;i++){ int d = tid + i*256; xr[d] = v[i]*scale*lw[d]; }
}

// ---------------- causal conv (K=4) + SiLU, both directions ----------------
__global__ void conv_k(const float* __restrict__ xz, const float* __restrict__ cw,
                       const float* __restrict__ cb, float* __restrict__ c)
{
    int d = blockIdx.x*256 + threadIdx.x;   // 0..1535
    int t = blockIdx.y;                     // 0..512
    int z = blockIdx.z; int b = z >> 1; int dir = z & 1;
    const float* cwd = cw + (i64)(dir*DI + d)*4;
    float acc = cb[dir*DI + d];
    #pragma unroll
    for (int k=0;k<4;k++){
        int tt = t - 3 + k;
        if (tt < 0) continue;
        int src = dir ? (NPATCH - tt) : tt;   // 512 - tt
        acc += xz[(i64)(b*LTOK + src)*DX + d] * cwd[k];
    }
    c[(i64)(dir*ROWS + b*LTOK + t)*DI + d] = siluf(acc);
}

// ---------------- sequential selective scan (thread per (b,dir,d), 16 states in regs) ----------------
__global__ void __launch_bounds__(256) scan_k(
    const float* __restrict__ c, const float* __restrict__ dt,
    const float* __restrict__ dbl, const float* __restrict__ xz,
    const float* __restrict__ alog, const float* __restrict__ dd,
    float* __restrict__ y)
{
    int d = blockIdx.x*256 + threadIdx.x;   // 0..1535
    int b = blockIdx.y, dir = blockIdx.z;
    const float LOG2E = 1.4426950408889634f;
    float A2[DST];
    #pragma unroll
    for (int s=0;s<DST;s++) A2[s] = -__expf(alog[(i64)(dir*DI + d)*DST + s]) * LOG2E;
    float Dv = dd[dir*DI + d];
    float h[DST];
    #pragma unroll
    for (int s=0;s<DST;s++) h[s] = 0.f;

    i64 base = (i64)(dir*ROWS + b*LTOK)*DI + d;
    const float* dblp = dbl + (i64)(dir*ROWS + b*LTOK)*DBLN;
    const float* zp = xz + (i64)(b*LTOK)*DX + DI + d;

    for (int t=0;t<LTOK;t++){
        float dtv = dt[base + (i64)t*DI];
        float cv  = c [base + (i64)t*DI];
        const float4* br = reinterpret_cast<const float4*>(dblp + t*DBLN + DTR);
        float Bv[DST], Cv[DST];
        *reinterpret_cast<float4*>(&Bv[0])  = br[0];
        *reinterpret_cast<float4*>(&Bv[4])  = br[1];
        *reinterpret_cast<float4*>(&Bv[8])  = br[2];
        *reinterpret_cast<float4*>(&Bv[12]) = br[3];
        *reinterpret_cast<float4*>(&Cv[0])  = br[4];
        *reinterpret_cast<float4*>(&Cv[4])  = br[5];
        *reinterpret_cast<float4*>(&Cv[8])  = br[6];
        *reinterpret_cast<float4*>(&Cv[12]) = br[7];
        float du = dtv * cv;
        float y0=0.f, y1=0.f, y2=0.f, y3=0.f;
        #pragma unroll
        for (int s=0;s<DST;s+=4){
            float dA0 = exp2f(dtv*A2[s+0]);
            float dA1 = exp2f(dtv*A2[s+1]);
            float dA2_ = exp2f(dtv*A2[s+2]);
            float dA3 = exp2f(dtv*A2[s+3]);
            h[s+0] = dA0*h[s+0] + du*Bv[s+0];
            h[s+1] = dA1*h[s+1] + du*Bv[s+1];
            h[s+2] = dA2_*h[s+2] + du*Bv[s+2];
            h[s+3] = dA3*h[s+3] + du*Bv[s+3];
            y0 += h[s+0]*Cv[s+0];
            y1 += h[s+1]*Cv[s+1];
            y2 += h[s+2]*Cv[s+2];
            y3 += h[s+3]*Cv[s+3];
        }
        float yv = (y0+y1)+(y2+y3) + cv*Dv;
        int zt = dir ? (NPATCH - t) : t;
        float zv = zp[(i64)zt*DX];
        yv *= siluf(zv);
        y[base + (i64)t*DI] = yv;
    }
}

// ---------------- combine: yc[b,t,d] = 0.5*(y_f[b,t,d] + y_b[b,512-t,d]) ----------------
__global__ void combine_k(const float* __restrict__ y, float* __restrict__ yc){
    i64 idx = (i64)blockIdx.x*256 + threadIdx.x;
    if (idx >= (i64)ROWS*DI) return;
    int d = (int)(idx % DI);
    i64 row = idx / DI;
    int b = (int)(row / LTOK); int t = (int)(row % LTOK);
    float a = y[idx];
    float bb = y[(i64)(ROWS + b*LTOK + (NPATCH - t))*DI + d];
    yc[idx] = 0.5f*(a + bb);
}

// ---------------- final: layer_norm(res[:,0] + h[:,0]) ----------------
__global__ void __launch_bounds__(256) final_k(
    const float* __restrict__ res, const float* __restrict__ h,
    const float* __restrict__ fw, const float* __restrict__ fb, float* __restrict__ out)
{
    int b = blockIdx.x; int tid = threadIdx.x;
    const float* rr = res + (i64)(b*LTOK)*DM;
    const float* hr = h + (i64)(b*LTOK)*DM;
    float v[3]; float s = 0.f;
    #pragma unroll
    for (int i=0;i<3;i++){ int d = tid + i*256; v[i] = rr[d] + hr[d]; s += v[i]; }
    __shared__ float red[256];
    red[tid] = s; __syncthreads();
    for (int st=128; st>0; st>>=1){ if (tid < st) red[tid] += red[tid+st]; __syncthreads(); }
    float mean = red[0] / (float)DM;
    __syncthreads();
    float q = 0.f;
    #pragma unroll
    for (int i=0;i<3;i++){ float t = v[i]-mean; q += t*t; }
    red[tid] = q; __syncthreads();
    for (int st=128; st>0; st>>=1){ if (tid < st) red[tid] += red[tid+st]; __syncthreads(); }
    float iv = rsqrtf(red[0]/(float)DM + 1e-5f);
    #pragma unroll
    for (int i=0;i<3;i++){ int d = tid + i*256; out[b*DM + d] = (v[i]-mean)*iv*fw[d] + fb[d]; }
}

// ---------------- host orchestration ----------------
extern "C" void kernel_launch(void* const* d_in, const int* in_sizes, int n_in,
                              void* d_out, int out_size)
{
    const float* x       = (const float*)d_in[0];
    const float* patch_w = (const float*)d_in[1];
    const float* patch_b = (const float*)d_in[2];
    const float* cls     = (const float*)d_in[3];
    const float* pos     = (const float*)d_in[4];
    const float* ln_w    = (const float*)d_in[5];
    const float* w_in    = (const float*)d_in[6];
    const float* conv_w  = (const float*)d_in[7];
    const float* conv_b  = (const float*)d_in[8];
    const float* w_x     = (const float*)d_in[9];
    const float* w_dt    = (const float*)d_in[10];
    const float* b_dt    = (const float*)d_in[11];
    const float* a_log   = (const float*)d_in[12];
    const float* dd      = (const float*)d_in[13];
    const float* w_out   = (const float*)d_in[14];
    const float* fn_w    = (const float*)d_in[15];
    const float* fn_b    = (const float*)d_in[16];

    float *xp,*h,*res,*xn,*xz,*c,*dblb,*dtb,*y,*yc;
    cudaGetSymbolAddress((void**)&xp,  g_xp);
    cudaGetSymbolAddress((void**)&h,   g_h);
    cudaGetSymbolAddress((void**)&res, g_res);
    cudaGetSymbolAddress((void**)&xn,  g_xn);
    cudaGetSymbolAddress((void**)&xz,  g_xz);
    cudaGetSymbolAddress((void**)&c,   g_c);
    cudaGetSymbolAddress((void**)&dblb,g_dbl);
    cudaGetSymbolAddress((void**)&dtb, g_dt);
    cudaGetSymbolAddress((void**)&y,   g_y);
    cudaGetSymbolAddress((void**)&yc,  g_yc);

    // patch embed
    gather_xp_k<<<(BATCH*NPATCH*PKK + 255)/256, 256>>>(x, xp);
    cls_fill_k<<<(BATCH*DM + 255)/256, 256>>>(cls, pos, h);
    sgemm_k<<<dim3(DM/GBN, (BATCH*NPATCH + GBM-1)/GBM, 1), 256>>>(
        xp, patch_w, h, BATCH*NPATCH, DM, PKK, PKK, PKK, DM,
        0, 0, 0, EPI_PATCH, patch_b, 0, pos);

    for (int l=0; l<DEPTH; l++){
        addrms_k<<<ROWS, 256>>>(res, h, xn, ln_w + (i64)l*DM, l==0 ? 1 : 0);

        // xz = xn @ w_in[l]^T : (2052,768)x(3072,768)
        sgemm_k<<<dim3(DX/GBN, (ROWS+GBM-1)/GBM, 1), 256>>>(
            xn, w_in + (i64)l*DX*DM, xz, ROWS, DX, DM, DM, DM, DX,
            0, 0, 0, EPI_PLAIN, nullptr, 0, nullptr);

        conv_k<<<dim3(DI/256, LTOK, BATCH*2), 256>>>(
            xz, conv_w + (i64)l*2*DI*4, conv_b + (i64)l*2*DI, c);

        // dbl[dir] = c[dir] @ w_x[l,dir]^T : (2052,1536)x(80,1536)
        sgemm_k<<<dim3(1, (ROWS+GBM-1)/GBM, 2), 256>>>(
            c, w_x + (i64)l*2*DBLN*DI, dblb, ROWS, DBLN, DI, DI, DI, DBLN,
            (i64)ROWS*DI, (i64)DBLN*DI, (i64)ROWS*DBLN, EPI_PLAIN, nullptr, 0, nullptr);

        // dt[dir] = softplus(dbl[:, :48] @ w_dt[l,dir]^T + b_dt[l,dir]) : (2052,80 lda)x(1536,48)
        sgemm_k<<<dim3(DI/GBN, (ROWS+GBM-1)/GBM, 2), 256>>>(
            dblb, w_dt + (i64)l*2*DI*DTR, dtb, ROWS, DI, DTR, DBLN, DTR, DI,
            (i64)ROWS*DBLN, (i64)DI*DTR, (i64)ROWS*DI, EPI_SOFTPLUS,
            b_dt + (i64)l*2*DI, (i64)DI, nullptr);

        scan_k<<<dim3(DI/256, BATCH, 2), 256>>>(
            c, dtb, dblb, xz, a_log + (i64)l*2*DI*DST, dd + (i64)l*2*DI, y);

        combine_k<<<(int)(((i64)ROWS*DI + 255)/256), 256>>>(y, yc);

        // h = yc @ w_out[l]^T : (2052,1536)x(768,1536)
        sgemm_k<<<dim3(DM/GBN, (ROWS+GBM-1)/GBM, 1), 256>>>(
            yc, w_out + (i64)l*DM*DI, h, ROWS, DM, DI, DI, DI, DM,
            0, 0, 0, EPI_PLAIN, nullptr, 0, nullptr);
    }

    final_k<<<BATCH, 256>>>(res, h, fn_w, fn_b, (float*)d_out);
}

// round 2
// speedup vs baseline: 1.0222x; 1.0222x over previous
#include <cuda_runtime.h>
#include <cuda_bf16.h>

// ---------------- problem constants ----------------
#define BATCH 4
#define LTOK 513          // N_PATCH + 1
#define NPATCH 512
#define ROWS (BATCH*LTOK) // 2052
#define DM 768
#define DI 1536
#define DX 3072           // 2*DI
#define DTR 48
#define DST 16
#define DBLN 80           // DTR + 2*DST
#define DEPTH 24
#define PKK 256           // 16*16 patch

typedef unsigned long long u64;
typedef long long i64;

// ---------------- scratch (static device memory; no allocation) ----------------
__device__ __align__(256) float g_xp [BATCH*NPATCH*PKK];
__device__ __align__(256) float g_h  [ROWS*DM];
__device__ __align__(256) float g_res[ROWS*DM];
__device__ __align__(256) float g_xn [ROWS*DM];
__device__ __align__(256) float g_xz [ROWS*DX];
__device__ __align__(256) float g_c  [2*ROWS*DI];
__device__ __align__(256) float g_dbl[2*ROWS*DBLN];
__device__ __align__(256) float g_dt [2*ROWS*DI];
__device__ __align__(256) float g_y  [2*ROWS*DI];
__device__ __align__(256) float g_yc [ROWS*DI];

// ---------------- f32x2 packed-FMA helpers (sm_100+) ----------------
__device__ __forceinline__ u64 pk2(float x, float y){
    u64 r; asm("mov.b64 %0,{%1,%2};" : "=l"(r) : "f"(x), "f"(y)); return r;
}
__device__ __forceinline__ void upk2(u64 v, float &x, float &y){
    asm("mov.b64 {%0,%1},%2;" : "=f"(x), "=f"(y) : "l"(v));
}
__device__ __forceinline__ u64 ffma2(u64 a, u64 b, u64 c){
    u64 d; asm("fma.rn.f32x2 %0,%1,%2,%3;" : "=l"(d) : "l"(a), "l"(b), "l"(c)); return d;
}

__device__ __forceinline__ float softplusf(float x){
    return x > 20.f ? x : log1pf(__expf(x));
}
__device__ __forceinline__ float siluf(float x){
    return x / (1.f + __expf(-x));
}

// ---------------- generic SGEMM: C[M,N] = A[M,K] * B[N,K]^T  (+ epilogues) ----------------
// 128x128 block tile, BK=16, 8x8 per thread, 256 threads, packed f32x2 FMA.
// Requires: K % 16 == 0, lda/ldb multiples of 4, bases 16B-aligned.
#define GBM 128
#define GBN 128
#define GBK 16
#define GTM 8
#define GTN 8
#define EPI_PLAIN 0
#define EPI_PATCH 1
#define EPI_SOFTPLUS 2

__global__ void __launch_bounds__(256,2) sgemm_k(
    const float* __restrict__ A, const float* __restrict__ Bw, float* __restrict__ C,
    int M, int N, int K, int lda, int ldb, int ldc,
    i64 bsA, i64 bsB, i64 bsC,
    int mode, const float* __restrict__ bias, i64 bsBias,
    const float* __restrict__ pos)
{
    A  += (i64)blockIdx.z * bsA;
    Bw += (i64)blockIdx.z * bsB;
    C  += (i64)blockIdx.z * bsC;
    if (bias) bias += (i64)blockIdx.z * bsBias;

    __shared__ float As[GBK][GBM+4];
    __shared__ float Bs[GBK][GBN+4];

    const int tid = threadIdx.x;
    const int m0 = blockIdx.y * GBM;
    const int n0 = blockIdx.x * GBN;
    const int lr = tid >> 2;            // 0..63
    const int lk = (tid & 3) * 4;       // 0,4,8,12
    const int tr = (tid >> 4) * GTM;    // 0..120
    const int tc = (tid & 15) * GTN;    // 0..120

    u64 acc[GTM][GTN/2];
    #pragma unroll
    for (int i=0;i<GTM;i++)
        #pragma unroll
        for (int j=0;j<GTN/2;j++) acc[i][j] = 0ULL;

    for (int k0 = 0; k0 < K; k0 += GBK) {
        #pragma unroll
        for (int hh=0; hh<2; hh++) {
            int r = lr + hh*64;
            int am = m0 + r;
            float4 av = make_float4(0.f,0.f,0.f,0.f);
            if (am < M) av = *reinterpret_cast<const float4*>(A + (i64)am*lda + (k0+lk));
            As[lk+0][r]=av.x; As[lk+1][r]=av.y; As[lk+2][r]=av.z; As[lk+3][r]=av.w;
            int bn = n0 + r;
            float4 bv = make_float4(0.f,0.f,0.f,0.f);
            if (bn < N) bv = *reinterpret_cast<const float4*>(Bw + (i64)bn*ldb + (k0+lk));
            Bs[lk+0][r]=bv.x; Bs[lk+1][r]=bv.y; Bs[lk+2][r]=bv.z; Bs[lk+3][r]=bv.w;
        }
        __syncthreads();
        #pragma unroll
        for (int k=0;k<GBK;k++) {
            float a[GTM];
            *reinterpret_cast<float4*>(&a[0]) = *reinterpret_cast<const float4*>(&As[k][tr]);
            *reinterpret_cast<float4*>(&a[4]) = *reinterpret_cast<const float4*>(&As[k][tr+4]);
            u64 bfrag[GTN/2];
            const u64* bp = reinterpret_cast<const u64*>(&Bs[k][tc]);
            bfrag[0]=bp[0]; bfrag[1]=bp[1]; bfrag[2]=bp[2]; bfrag[3]=bp[3];
            #pragma unroll
            for (int i=0;i<GTM;i++) {
                u64 a2 = pk2(a[i], a[i]);
                #pragma unroll
                for (int j=0;j<GTN/2;j++)
                    acc[i][j] = ffma2(a2, bfrag[j], acc[i][j]);
            }
        }
        __syncthreads();
    }

    #pragma unroll
    for (int i=0;i<GTM;i++) {
        int m = m0 + tr + i;
        if (m >= M) continue;
        #pragma unroll
        for (int j=0;j<GTN/2;j++) {
            int n = n0 + tc + 2*j;
            if (n >= N) continue;
            float x, y;
            upk2(acc[i][j], x, y);
            if (mode == EPI_PLAIN) {
                if (n+1 < N) *reinterpret_cast<float2*>(C + (i64)m*ldc + n) = make_float2(x,y);
                else C[(i64)m*ldc + n] = x;
            } else if (mode == EPI_SOFTPLUS) {
                x = softplusf(x + bias[n]);
                if (n+1 < N) {
                    y = softplusf(y + bias[n+1]);
                    *reinterpret_cast<float2*>(C + (i64)m*ldc + n) = make_float2(x,y);
                } else C[(i64)m*ldc + n] = x;
            } else { // EPI_PATCH: remap patch rows -> token rows (skip CLS), add patch_b + pos_embed
                int p = m & (NPATCH-1);
                int row = (m >> 9)*LTOK + p + 1;
                float2 v;
                v.x = x + bias[n]   + pos[(i64)(p+1)*DM + n];
                v.y = y + bias[n+1] + pos[(i64)(p+1)*DM + n + 1];
                *reinterpret_cast<float2*>(C + (i64)row*ldc + n) = v;
            }
        }
    }
}

// ---------------- patch gather: xp[b, f*64+t, i*16+j] = x[b, f*16+i, t*16+j] ----------------
__global__ void gather_xp_k(const float* __restrict__ x, float* __restrict__ xp){
    i64 idx = (i64)blockIdx.x*256 + threadIdx.x;
    if (idx >= (i64)BATCH*NPATCH*PKK) return;
    int k = (int)(idx & 255);
    int p = (int)((idx >> 8) & 511);
    int b = (int)(idx >> 17);
    int i = k >> 4, j = k & 15;
    int f = p >> 6, t = p & 63;
    xp[idx] = x[(i64)(b*128 + f*16 + i)*1024 + t*16 + j];
}

// ---------------- cls row fill: h[b,0,:] = cls + pos[0,:] ----------------
__global__ void cls_fill_k(const float* __restrict__ cls, const float* __restrict__ pos,
                           float* __restrict__ h){
    int idx = blockIdx.x*256 + threadIdx.x;
    if (idx >= BATCH*DM) return;
    int b = idx / DM, d = idx % DM;
    h[(i64)(b*LTOK)*DM + d] = cls[d] + pos[d];
}

// ---------------- res = (first ? h : res + h); xn = rms_norm(res)*lw ----------------
__global__ void __launch_bounds__(256) addrms_k(
    float* __restrict__ res, const float* __restrict__ h, float* __restrict__ xn,
    const float* __restrict__ lw, int first)
{
    int r = blockIdx.x;
    const float* hr = h + (i64)r*DM;
    float* rr = res + (i64)r*DM;
    float* xr = xn + (i64)r*DM;
    int tid = threadIdx.x;
    float v[3]; float ss = 0.f;
    #pragma unroll
    for (int i=0;i<3;i++){
        int d = tid + i*256;
        float t = first ? hr[d] : (rr[d] + hr[d]);
        v[i] = t; rr[d] = t; ss += t*t;
    }
    __shared__ float red[256];
    red[tid] = ss; __syncthreads();
    for (int s=128; s>0; s>>=1){ if (tid < s) red[tid] += red[tid+s]; __syncthreads(); }
    float scale = rsqrtf(red[0]/(float)DM + 1e-5f);
    #pragma unroll
    for (int i=0;i<3;i++){ int d = tid + i*256; xr[d] = v[i]*scale*lw[d]; }
}

// ---------------- causal conv (K=4) + SiLU, both directions ----------------
__global__ void conv_k(const float* __restrict__ xz, const float* __restrict__ cw,
                       const float* __restrict__ cb, float* __restrict__ c)
{
    int d = blockIdx.x*256 + threadIdx.x;   // 0..1535
    int t = blockIdx.y;                     // 0..512
    int z = blockIdx.z; int b = z >> 1; int dir = z & 1;
    const float* cwd = cw + (i64)(dir*DI + d)*4;
    float acc = cb[dir*DI + d];
    #pragma unroll
    for (int k=0;k<4;k++){
        int tt = t - 3 + k;
        if (tt < 0) continue;
        int src = dir ? (NPATCH - tt) : tt;   // 512 - tt
        acc += xz[(i64)(b*LTOK + src)*DX + d] * cwd[k];
    }
    c[(i64)(dir*ROWS + b*LTOK + t)*DI + d] = siluf(acc);
}

// ---------------- sequential selective scan (thread per (b,dir,d), 16 states in regs) ----------------
__global__ void __launch_bounds__(256) scan_k(
    const float* __restrict__ c, const float* __restrict__ dt,
    const float* __restrict__ dbl, const float* __restrict__ xz,
    const float* __restrict__ alog, const float* __restrict__ dd,
    float* __restrict__ y)
{
    int d = blockIdx.x*256 + threadIdx.x;   // 0..1535
    int b = blockIdx.y, dir = blockIdx.z;
    const float LOG2E = 1.4426950408889634f;
    float A2[DST];
    #pragma unroll
    for (int s=0;s<DST;s++) A2[s] = -__expf(alog[(i64)(dir*DI + d)*DST + s]) * LOG2E;
    float Dv = dd[dir*DI + d];
    float h[DST];
    #pragma unroll
    for (int s=0;s<DST;s++) h[s] = 0.f;

    i64 base = (i64)(dir*ROWS + b*LTOK)*DI + d;
    const float* dblp = dbl + (i64)(dir*ROWS + b*LTOK)*DBLN;
    const float* zp = xz + (i64)(b*LTOK)*DX + DI + d;

    for (int t=0;t<LTOK;t++){
        float dtv = dt[base + (i64)t*DI];
        float cv  = c [base + (i64)t*DI];
        const float4* br = reinterpret_cast<const float4*>(dblp + t*DBLN + DTR);
        float Bv[DST], Cv[DST];
        *reinterpret_cast<float4*>(&Bv[0])  = br[0];
        *reinterpret_cast<float4*>(&Bv[4])  = br[1];
        *reinterpret_cast<float4*>(&Bv[8])  = br[2];
        *reinterpret_cast<float4*>(&Bv[12]) = br[3];
        *reinterpret_cast<float4*>(&Cv[0])  = br[4];
        *reinterpret_cast<float4*>(&Cv[4])  = br[5];
        *reinterpret_cast<float4*>(&Cv[8])  = br[6];
        *reinterpret_cast<float4*>(&Cv[12]) = br[7];
        float du = dtv * cv;
        float y0=0.f, y1=0.f, y2=0.f, y3=0.f;
        #pragma unroll
        for (int s=0;s<DST;s+=4){
            float dA0 = exp2f(dtv*A2[s+0]);
            float dA1 = exp2f(dtv*A2[s+1]);
            float dA2_ = exp2f(dtv*A2[s+2]);
            float dA3 = exp2f(dtv*A2[s+3]);
            h[s+0] = dA0*h[s+0] + du*Bv[s+0];
            h[s+1] = dA1*h[s+1] + du*Bv[s+1];
            h[s+2] = dA2_*h[s+2] + du*Bv[s+2];
            h[s+3] = dA3*h[s+3] + du*Bv[s+3];
            y0 += h[s+0]*Cv[s+0];
            y1 += h[s+1]*Cv[s+1];
            y2 += h[s+2]*Cv[s+2];
            y3 += h[s+3]*Cv[s+3];
        }
        float yv = (y0+y1)+(y2+y3) + cv*Dv;
        int zt = dir ? (NPATCH - t) : t;
        float zv = zp[(i64)zt*DX];
        yv *= siluf(zv);
        y[base + (i64)t*DI] = yv;
    }
}

// ---------------- combine: yc[b,t,d] = 0.5*(y_f[b,t,d] + y_b[b,512-t,d]) ----------------
__global__ void combine_k(const float* __restrict__ y, float* __restrict__ yc){
    i64 idx = (i64)blockIdx.x*256 + threadIdx.x;
    if (idx >= (i64)ROWS*DI) return;
    int d = (int)(idx % DI);
    i64 row = idx / DI;
    int b = (int)(row / LTOK); int t = (int)(row % LTOK);
    float a = y[idx];
    float bb = y[(i64)(ROWS + b*LTOK + (NPATCH - t))*DI + d];
    yc[idx] = 0.5f*(a + bb);
}

// ---------------- final: layer_norm(res[:,0] + h[:,0]) ----------------
__global__ void __launch_bounds__(256) final_k(
    const float* __restrict__ res, const float* __restrict__ h,
    const float* __restrict__ fw, const float* __restrict__ fb, float* __restrict__ out)
{
    int b = blockIdx.x; int tid = threadIdx.x;
    const float* rr = res + (i64)(b*LTOK)*DM;
    const float* hr = h + (i64)(b*LTOK)*DM;
    float v[3]; float s = 0.f;
    #pragma unroll
    for (int i=0;i<3;i++){ int d = tid + i*256; v[i] = rr[d] + hr[d]; s += v[i]; }
    __shared__ float red[256];
    red[tid] = s; __syncthreads();
    for (int st=128; st>0; st>>=1){ if (tid < st) red[tid] += red[tid+st]; __syncthreads(); }
    float mean = red[0] / (float)DM;
    __syncthreads();
    float q = 0.f;
    #pragma unroll
    for (int i=0;i<3;i++){ float t = v[i]-mean; q += t*t; }
    red[tid] = q; __syncthreads();
    for (int st=128; st>0; st>>=1){ if (tid < st) red[tid] += red[tid+st]; __syncthreads(); }
    float iv = rsqrtf(red[0]/(float)DM + 1e-5f);
    #pragma unroll
    for (int i=0;i<3;i++){ int d = tid + i*256; out[b*DM + d] = (v[i]-mean)*iv*fw[d] + fb[d]; }
}

// ---------------- host orchestration ----------------
extern "C" void kernel_launch(void* const* d_in, const int* in_sizes, int n_in,
                              void* d_out, int out_size)
{
    const float* x       = (const float*)d_in[0];
    const float* patch_w = (const float*)d_in[1];
    const float* patch_b = (const float*)d_in[2];
    const float* cls     = (const float*)d_in[3];
    const float* pos     = (const float*)d_in[4];
    const float* ln_w    = (const float*)d_in[5];
    const float* w_in    = (const float*)d_in[6];
    const float* conv_w  = (const float*)d_in[7];
    const float* conv_b  = (const float*)d_in[8];
    const float* w_x     = (const float*)d_in[9];
    const float* w_dt    = (const float*)d_in[10];
    const float* b_dt    = (const float*)d_in[11];
    const float* a_log   = (const float*)d_in[12];
    const float* dd      = (const float*)d_in[13];
    const float* w_out   = (const float*)d_in[14];
    const float* fn_w    = (const float*)d_in[15];
    const float* fn_b    = (const float*)d_in[16];

    float *xp,*h,*res,*xn,*xz,*c,*dblb,*dtb,*y,*yc;
    cudaGetSymbolAddress((void**)&xp,  g_xp);
    cudaGetSymbolAddress((void**)&h,   g_h);
    cudaGetSymbolAddress((void**)&res, g_res);
    cudaGetSymbolAddress((void**)&xn,  g_xn);
    cudaGetSymbolAddress((void**)&xz,  g_xz);
    cudaGetSymbolAddress((void**)&c,   g_c);
    cudaGetSymbolAddress((void**)&dblb,g_dbl);
    cudaGetSymbolAddress((void**)&dtb, g_dt);
    cudaGetSymbolAddress((void**)&y,   g_y);
    cudaGetSymbolAddress((void**)&yc,  g_yc);

    // patch embed
    gather_xp_k<<<(BATCH*NPATCH*PKK + 255)/256, 256>>>(x, xp);
    cls_fill_k<<<(BATCH*DM + 255)/256, 256>>>(cls, pos, h);
    sgemm_k<<<dim3(DM/GBN, (BATCH*NPATCH + GBM-1)/GBM, 1), 256>>>(
        xp, patch_w, h, BATCH*NPATCH, DM, PKK, PKK, PKK, DM,
        0, 0, 0, EPI_PATCH, patch_b, 0, pos);

    for (int l=0; l<DEPTH; l++){
        addrms_k<<<ROWS, 256>>>(res, h, xn, ln_w + (i64)l*DM, l==0 ? 1 : 0);

        // xz = xn @ w_in[l]^T : (2052,768)x(3072,768)
        sgemm_k<<<dim3(DX/GBN, (ROWS+GBM-1)/GBM, 1), 256>>>(
            xn, w_in + (i64)l*DX*DM, xz, ROWS, DX, DM, DM, DM, DX,
            0, 0, 0, EPI_PLAIN, nullptr, 0, nullptr);

        conv_k<<<dim3(DI/256, LTOK, BATCH*2), 256>>>(
            xz, conv_w + (i64)l*2*DI*4, conv_b + (i64)l*2*DI, c);

        // dbl[dir] = c[dir] @ w_x[l,dir]^T : (2052,1536)x(80,1536)
        sgemm_k<<<dim3(1, (ROWS+GBM-1)/GBM, 2), 256>>>(
            c, w_x + (i64)l*2*DBLN*DI, dblb, ROWS, DBLN, DI, DI, DI, DBLN,
            (i64)ROWS*DI, (i64)DBLN*DI, (i64)ROWS*DBLN, EPI_PLAIN, nullptr, 0, nullptr);

        // dt[dir] = softplus(dbl[:, :48] @ w_dt[l,dir]^T + b_dt[l,dir]) : (2052,80 lda)x(1536,48)
        sgemm_k<<<dim3(DI/GBN, (ROWS+GBM-1)/GBM, 2), 256>>>(
            dblb, w_dt + (i64)l*2*DI*DTR, dtb, ROWS, DI, DTR, DBLN, DTR, DI,
            (i64)ROWS*DBLN, (i64)DI*DTR, (i64)ROWS*DI, EPI_SOFTPLUS,
            b_dt + (i64)l*2*DI, (i64)DI, nullptr);

        scan_k<<<dim3(DI/256, BATCH, 2), 256>>>(
            c, dtb, dblb, xz, a_log + (i64)l*2*DI*DST, dd + (i64)l*2*DI, y);

        combine_k<<<(int)(((i64)ROWS*DI + 255)/256), 256>>>(y, yc);

        // h = yc @ w_out[l]^T : (2052,1536)x(768,1536)
        sgemm_k<<<dim3(DM/GBN, (ROWS+GBM-1)/GBM, 1), 256>>>(
            yc, w_out + (i64)l*DM*DI, h, ROWS, DM, DI, DI, DI, DM,
            0, 0, 0, EPI_PLAIN, nullptr, 0, nullptr);
    }

    final_k<<<BATCH, 256>>>(res, h, fn_w, fn_b, (float*)d_out);
}

// round 4
// speedup vs baseline: 1.2501x; 1.2230x over previous
#include <cuda_runtime.h>
#include <cuda_bf16.h>

typedef unsigned int u32;
typedef unsigned long long u64;
typedef long long i64;

#define BATCH 4
#define LTOK 513
#define NPATCH 512
#define ROWS (BATCH*LTOK)
#define DM 768
#define DI 1536
#define DX 3072
#define DTR 48
#define DST 16
#define DBLN 80
#define DEPTH 24
#define PKK 256

// ---------------- fp32 scratch ----------------
__device__ __align__(256) float g_h  [ROWS*DM];
__device__ __align__(256) float g_res[ROWS*DM];
__device__ __align__(256) float g_xz [ROWS*DX];
__device__ __align__(256) float g_c  [2*ROWS*DI];
__device__ __align__(256) float g_dbl[2*ROWS*DBLN];
__device__ __align__(256) float g_dt [2*ROWS*DI];
__device__ __align__(256) float g_y  [2*ROWS*DI];

// ---------------- bf16 hi|lo split buffers (row = [hi(Kp) | lo(Kp)], pitch 2*Kp elems) ----------------
__device__ __align__(256) __nv_bfloat16 g_winb [DEPTH*DX*2*DM];
__device__ __align__(256) __nv_bfloat16 g_wxb  [DEPTH*2*DBLN*2*DI];
__device__ __align__(256) __nv_bfloat16 g_wdtb [DEPTH*2*DI*128];
__device__ __align__(256) __nv_bfloat16 g_woutb[DEPTH*DM*2*DI];
__device__ __align__(256) __nv_bfloat16 g_pwb  [DM*2*PKK];
__device__ __align__(256) __nv_bfloat16 g_xnb  [ROWS*2*DM];
__device__ __align__(256) __nv_bfloat16 g_cb   [2*ROWS*2*DI];
__device__ __align__(256) __nv_bfloat16 g_dtAb [2*ROWS*128];
__device__ __align__(256) __nv_bfloat16 g_ycb  [ROWS*2*DI];
__device__ __align__(256) __nv_bfloat16 g_xpb  [BATCH*NPATCH*2*PKK];

__device__ __forceinline__ float softplusf(float x){ return x > 20.f ? x : log1pf(__expf(x)); }
__device__ __forceinline__ float siluf(float x){ return x / (1.f + __expf(-x)); }

__device__ __forceinline__ u32 smem_u32(const void* p){
    u32 a; asm("{ .reg .u64 t; cvta.to.shared.u64 t, %1; cvt.u32.u64 %0, t; }" : "=r"(a) : "l"(p)); return a;
}
__device__ __forceinline__ void cpa16(u32 d, const void* g, int sz){
    asm volatile("cp.async.cg.shared.global [%0], [%1], 16, %2;" :: "r"(d), "l"(g), "r"(sz) : "memory");
}
__device__ __forceinline__ void ldm_x4(u32 a, u32& r0, u32& r1, u32& r2, u32& r3){
    asm volatile("ldmatrix.sync.aligned.m8n8.x4.shared.b16 {%0,%1,%2,%3}, [%4];"
        : "=r"(r0), "=r"(r1), "=r"(r2), "=r"(r3) : "r"(a));
}
__device__ __forceinline__ void mma16816(float* c, u32 a0,u32 a1,u32 a2,u32 a3, u32 b0,u32 b1){
    asm volatile("mma.sync.aligned.m16n8k16.row.col.f32.bf16.bf16.f32 "
        "{%0,%1,%2,%3}, {%4,%5,%6,%7}, {%8,%9}, {%0,%1,%2,%3};"
        : "+f"(c[0]),"+f"(c[1]),"+f"(c[2]),"+f"(c[3])
        : "r"(a0),"r"(a1),"r"(a2),"r"(a3),"r"(b0),"r"(b1));
}

// ==================== split-bf16 HMMA GEMM ====================
// C[M,N] = A[M,K]*B[N,K]^T via 3 bf16 passes (Ahi*Bhi, Ahi*Blo, Alo*Bhi), fp32 reg accum.
// A,B rows: [hi | lo], 2*Kp bf16 (pitch 4*Kp bytes). Kp % 32 == 0. N % TN == 0.
// MODE: 0=plain  1=patch(row remap+bias+pos)  2=softplus(+bias)  3=plain + dtA aux
template<int TN, int MODE>
__global__ void __launch_bounds__(256) mma_gemm_k(
    const __nv_bfloat16* __restrict__ A, const __nv_bfloat16* __restrict__ B,
    float* __restrict__ C, int M, int Kp, int ldc,
    i64 bsA, i64 bsB, i64 bsC,
    const float* __restrict__ bias, i64 bsBias,
    const float* __restrict__ pos,
    __nv_bfloat16* __restrict__ aux, i64 bsAux)
{
    constexpr int S  = 3;
    constexpr int BK = 32;
    constexpr int AP = BK + 8;                 // 40-elem pitch (80B, 16B-aligned)
    constexpr int ABYTES = 128*AP*2;
    constexpr int BBYTES = TN*AP*2;
    constexpr int STG = ABYTES + BBYTES;
    constexpr int WM = (TN >= 128) ? 4 : 8;    // warp grid
    constexpr int WN = 8 / WM;
    constexpr int RW = 128 / WM;               // warp tile rows
    constexpr int CW = TN / WN;                // warp tile cols
    constexpr int MT = RW / 16;
    constexpr int NT = CW / 8;
    constexpr int TP = TN + 4;

    extern __shared__ __align__(16) char smem[];
    const u32 sb = smem_u32(smem);
    const int tid = threadIdx.x;
    const int wid = tid >> 5;
    const int lane = tid & 31;
    const int wm = wid / WN, wn = wid % WN;
    const int m0 = blockIdx.y * 128;
    const int n0 = blockIdx.x * TN;
    A += (i64)blockIdx.z * bsA;
    B += (i64)blockIdx.z * bsB;
    C += (i64)blockIdx.z * bsC;
    if (bias) bias += (i64)blockIdx.z * bsBias;
    if (aux)  aux  += (i64)blockIdx.z * bsAux;

    const int KC = Kp / BK;
    const int NC = 3*KC;
    const i64 pitch = 4*(i64)Kp;
    const char* Ab = (const char*)A;
    const char* Bb = (const char*)B;

    float acc[MT][NT][4];
    #pragma unroll
    for (int i=0;i<MT;i++)
        #pragma unroll
        for (int j=0;j<NT;j++)
            #pragma unroll
            for (int q=0;q<4;q++) acc[i][j][q] = 0.f;

    auto load_chunk = [&](int c){
        int pass = c / KC; int kk = c - pass*KC;
        int aColB = ((pass==2 ? Kp : 0) + kk*BK)*2;   // bytes
        int bColB = ((pass==1 ? Kp : 0) + kk*BK)*2;
        u32 as = sb + (c % S)*STG;
        u32 bs = as + ABYTES;
        #pragma unroll
        for (int s = tid; s < 128*4; s += 256){
            int row = s>>2, seg = s&3;
            int gm = m0 + row;
            int sz = (gm < M) ? 16 : 0;
            if (gm >= M) gm = 0;
            cpa16(as + row*(AP*2) + seg*16, Ab + (i64)gm*pitch + aColB + seg*16, sz);
        }
        for (int s = tid; s < TN*4; s += 256){
            int row = s>>2, seg = s&3;
            cpa16(bs + row*(AP*2) + seg*16, Bb + (i64)(n0+row)*pitch + bColB + seg*16, 16);
        }
        asm volatile("cp.async.commit_group;" ::: "memory");
    };

    load_chunk(0);
    load_chunk(1);

    const int lr = lane & 7;          // row within 8x8 matrix
    const int q1 = (lane >> 3) & 1;
    const int q2 = (lane >> 4);

    for (int i = 0; i < NC; i++){
        asm volatile("cp.async.wait_group 1;" ::: "memory");
        __syncthreads();
        if (i+2 < NC) load_chunk(i+2);
        u32 as = sb + (i % S)*STG;
        u32 bs = as + ABYTES;
        #pragma unroll
        for (int kk = 0; kk < 2; kk++){
            u32 af[MT][4];
            u32 bf[NT][2];
            #pragma unroll
            for (int mt = 0; mt < MT; mt++){
                int row = wm*RW + mt*16 + lr + q1*8;
                int col = kk*16 + q2*8;
                ldm_x4(as + (row*AP + col)*2, af[mt][0], af[mt][1], af[mt][2], af[mt][3]);
            }
            #pragma unroll
            for (int nt2 = 0; nt2 < NT/2; nt2++){
                int row = wn*CW + nt2*16 + q2*8 + lr;
                int col = kk*16 + q1*8;
                ldm_x4(bs + (row*AP + col)*2,
                       bf[2*nt2][0], bf[2*nt2][1], bf[2*nt2+1][0], bf[2*nt2+1][1]);
            }
            #pragma unroll
            for (int mt = 0; mt < MT; mt++)
                #pragma unroll
                for (int nt = 0; nt < NT; nt++)
                    mma16816(acc[mt][nt], af[mt][0], af[mt][1], af[mt][2], af[mt][3],
                             bf[nt][0], bf[nt][1]);
        }
    }
    asm volatile("cp.async.wait_group 0;" ::: "memory");
    __syncthreads();

    // ---------- epilogue: accum -> smem tile -> coalesced gmem ----------
    float* tile = (float*)smem;   // [128][TP]
    {
        int rbase = wm*RW + (lane >> 2);
        int cbase = wn*CW + (lane & 3)*2;
        #pragma unroll
        for (int mt = 0; mt < MT; mt++){
            #pragma unroll
            for (int nt = 0; nt < NT; nt++){
                int r = rbase + mt*16;
                int cc = cbase + nt*8;
                tile[r*TP + cc]       = acc[mt][nt][0];
                tile[r*TP + cc + 1]   = acc[mt][nt][1];
                tile[(r+8)*TP + cc]   = acc[mt][nt][2];
                tile[(r+8)*TP + cc+1] = acc[mt][nt][3];
            }
        }
    }
    __syncthreads();

    constexpr int V4 = 128*(TN/4);
    for (int v = tid; v < V4; v += 256){
        int row = v / (TN/4);
        int col = (v % (TN/4)) * 4;
        int m = m0 + row;
        if (m >= M) continue;
        float4 val;
        val.x = tile[row*TP + col+0];
        val.y = tile[row*TP + col+1];
        val.z = tile[row*TP + col+2];
        val.w = tile[row*TP + col+3];
        int n = n0 + col;
        if (MODE == 1){
            int p = m & 511, b = m >> 9;
            i64 crow = (i64)(b*LTOK + p + 1)*ldc;
            const float* posr = pos + (i64)(p+1)*DM;
            val.x += bias[n+0] + posr[n+0];
            val.y += bias[n+1] + posr[n+1];
            val.z += bias[n+2] + posr[n+2];
            val.w += bias[n+3] + posr[n+3];
            *reinterpret_cast<float4*>(C + crow + n) = val;
        } else if (MODE == 2){
            val.x = softplusf(val.x + bias[n+0]);
            val.y = softplusf(val.y + bias[n+1]);
            val.z = softplusf(val.z + bias[n+2]);
            val.w = softplusf(val.w + bias[n+3]);
            *reinterpret_cast<float4*>(C + (i64)m*ldc + n) = val;
        } else {
            *reinterpret_cast<float4*>(C + (i64)m*ldc + n) = val;
        }
    }
    if (MODE == 3){
        for (int v = tid; v < 128*64; v += 256){
            int row = v >> 6, col = v & 63;
            int m = m0 + row;
            if (m >= M) continue;
            float x = (col < DTR) ? tile[row*TP + col] : 0.f;
            __nv_bfloat16 hi = __float2bfloat16(x);
            aux[(i64)m*128 + col]      = hi;
            aux[(i64)m*128 + 64 + col] = __float2bfloat16(x - __bfloat162float(hi));
        }
    }
}

// ---------------- weight conversion: [rows,K] f32 -> [rows, 2*Kp] bf16 hi|lo (zero-pad) ----------------
__global__ void wconv_k(const float* __restrict__ src, __nv_bfloat16* __restrict__ dst,
                        int K, int Kp, i64 rows){
    i64 idx = (i64)blockIdx.x*256 + threadIdx.x;
    i64 tot = rows*(i64)Kp;
    if (idx >= tot) return;
    i64 n = idx / Kp; int k = (int)(idx - n*Kp);
    float v = (k < K) ? src[n*(i64)K + k] : 0.f;
    __nv_bfloat16 hi = __float2bfloat16(v);
    dst[n*(i64)(2*Kp) + k]      = hi;
    dst[n*(i64)(2*Kp) + Kp + k] = __float2bfloat16(v - __bfloat162float(hi));
}

// ---------------- patch gather + split ----------------
__global__ void gather_xp_k(const float* __restrict__ x, __nv_bfloat16* __restrict__ xpb){
    i64 idx = (i64)blockIdx.x*256 + threadIdx.x;
    if (idx >= (i64)BATCH*NPATCH*PKK) return;
    int k = (int)(idx & 255);
    int p = (int)((idx >> 8) & 511);
    int b = (int)(idx >> 17);
    int i = k >> 4, j = k & 15;
    int f = p >> 6, t = p & 63;
    float v = x[(i64)(b*128 + f*16 + i)*1024 + t*16 + j];
    __nv_bfloat16 hi = __float2bfloat16(v);
    i64 row = (i64)(b*NPATCH + p);
    xpb[row*512 + k]       = hi;
    xpb[row*512 + 256 + k] = __float2bfloat16(v - __bfloat162float(hi));
}

__global__ void cls_fill_k(const float* __restrict__ cls, const float* __restrict__ pos,
                           float* __restrict__ h){
    int idx = blockIdx.x*256 + threadIdx.x;
    if (idx >= BATCH*DM) return;
    int b = idx / DM, d = idx % DM;
    h[(i64)(b*LTOK)*DM + d] = cls[d] + pos[d];
}

// ---------------- res += h ; xnb = bf16split(rmsnorm(res)*lw) ----------------
__global__ void __launch_bounds__(256) addrms_k(
    float* __restrict__ res, const float* __restrict__ h, __nv_bfloat16* __restrict__ xnb,
    const float* __restrict__ lw, int first)
{
    int r = blockIdx.x;
    const float* hr = h + (i64)r*DM;
    float* rr = res + (i64)r*DM;
    __nv_bfloat16* xr = xnb + (i64)r*(2*DM);
    int tid = threadIdx.x;
    float v[3]; float ss = 0.f;
    #pragma unroll
    for (int i=0;i<3;i++){
        int d = tid + i*256;
        float t = first ? hr[d] : (rr[d] + hr[d]);
        v[i] = t; rr[d] = t; ss += t*t;
    }
    __shared__ float red[256];
    red[tid] = ss; __syncthreads();
    for (int s=128; s>0; s>>=1){ if (tid < s) red[tid] += red[tid+s]; __syncthreads(); }
    float scale = rsqrtf(red[0]/(float)DM + 1e-5f);
    #pragma unroll
    for (int i=0;i<3;i++){
        int d = tid + i*256;
        float o = v[i]*scale*lw[d];
        __nv_bfloat16 hi = __float2bfloat16(o);
        xr[d]      = hi;
        xr[DM + d] = __float2bfloat16(o - __bfloat162float(hi));
    }
}

// ---------------- causal conv + SiLU -> c (f32) + cb (bf16 split) ----------------
__global__ void conv_k(const float* __restrict__ xz, const float* __restrict__ cw,
                       const float* __restrict__ cb_, float* __restrict__ c,
                       __nv_bfloat16* __restrict__ cbb)
{
    int d = blockIdx.x*256 + threadIdx.x;
    int t = blockIdx.y;
    int z = blockIdx.z; int b = z >> 1; int dir = z & 1;
    const float* cwd = cw + (i64)(dir*DI + d)*4;
    float acc = cb_[dir*DI + d];
    #pragma unroll
    for (int k=0;k<4;k++){
        int tt = t - 3 + k;
        if (tt < 0) continue;
        int src = dir ? (NPATCH - tt) : tt;
        acc += xz[(i64)(b*LTOK + src)*DX + d] * cwd[k];
    }
    float o = siluf(acc);
    i64 row = (i64)(dir*ROWS + b*LTOK + t);
    c[row*DI + d] = o;
    __nv_bfloat16 hi = __float2bfloat16(o);
    cbb[row*(2*DI) + d]      = hi;
    cbb[row*(2*DI) + DI + d] = __float2bfloat16(o - __bfloat162float(hi));
}

// ---------------- sequential selective scan ----------------
__global__ void __launch_bounds__(256) scan_k(
    const float* __restrict__ c, const float* __restrict__ dt,
    const float* __restrict__ dbl, const float* __restrict__ xz,
    const float* __restrict__ alog, const float* __restrict__ dd,
    float* __restrict__ y)
{
    int d = blockIdx.x*256 + threadIdx.x;
    int b = blockIdx.y, dir = blockIdx.z;
    const float LOG2E = 1.4426950408889634f;
    float A2[DST];
    #pragma unroll
    for (int s=0;s<DST;s++) A2[s] = -__expf(alog[(i64)(dir*DI + d)*DST + s]) * LOG2E;
    float Dv = dd[dir*DI + d];
    float h[DST];
    #pragma unroll
    for (int s=0;s<DST;s++) h[s] = 0.f;

    i64 base = (i64)(dir*ROWS + b*LTOK)*DI + d;
    const float* dblp = dbl + (i64)(dir*ROWS + b*LTOK)*DBLN;
    const float* zp = xz + (i64)(b*LTOK)*DX + DI + d;

    for (int t=0;t<LTOK;t++){
        float dtv = dt[base + (i64)t*DI];
        float cv  = c [base + (i64)t*DI];
        const float4* br = reinterpret_cast<const float4*>(dblp + t*DBLN + DTR);
        float Bv[DST], Cv[DST];
        *reinterpret_cast<float4*>(&Bv[0])  = br[0];
        *reinterpret_cast<float4*>(&Bv[4])  = br[1];
        *reinterpret_cast<float4*>(&Bv[8])  = br[2];
        *reinterpret_cast<float4*>(&Bv[12]) = br[3];
        *reinterpret_cast<float4*>(&Cv[0])  = br[4];
        *reinterpret_cast<float4*>(&Cv[4])  = br[5];
        *reinterpret_cast<float4*>(&Cv[8])  = br[6];
        *reinterpret_cast<float4*>(&Cv[12]) = br[7];
        float du = dtv * cv;
        float y0=0.f, y1=0.f, y2=0.f, y3=0.f;
        #pragma unroll
        for (int s=0;s<DST;s+=4){
            float dA0 = exp2f(dtv*A2[s+0]);
            float dA1 = exp2f(dtv*A2[s+1]);
            float dA2_ = exp2f(dtv*A2[s+2]);
            float dA3 = exp2f(dtv*A2[s+3]);
            h[s+0] = dA0*h[s+0] + du*Bv[s+0];
            h[s+1] = dA1*h[s+1] + du*Bv[s+1];
            h[s+2] = dA2_*h[s+2] + du*Bv[s+2];
            h[s+3] = dA3*h[s+3] + du*Bv[s+3];
            y0 += h[s+0]*Cv[s+0];
            y1 += h[s+1]*Cv[s+1];
            y2 += h[s+2]*Cv[s+2];
            y3 += h[s+3]*Cv[s+3];
        }
        float yv = (y0+y1)+(y2+y3) + cv*Dv;
        int zt = dir ? (NPATCH - t) : t;
        float zv = zp[(i64)zt*DX];
        yv *= siluf(zv);
        y[base + (i64)t*DI] = yv;
    }
}

// ---------------- combine -> ycb (bf16 split) ----------------
__global__ void combine_k(const float* __restrict__ y, __nv_bfloat16* __restrict__ ycb){
    i64 idx = (i64)blockIdx.x*256 + threadIdx.x;
    if (idx >= (i64)ROWS*DI) return;
    int d = (int)(idx % DI);
    i64 row = idx / DI;
    int b = (int)(row / LTOK); int t = (int)(row % LTOK);
    float a = y[idx];
    float bb = y[(i64)(ROWS + b*LTOK + (NPATCH - t))*DI + d];
    float o = 0.5f*(a + bb);
    __nv_bfloat16 hi = __float2bfloat16(o);
    ycb[row*(2*DI) + d]      = hi;
    ycb[row*(2*DI) + DI + d] = __float2bfloat16(o - __bfloat162float(hi));
}

// ---------------- final layer_norm(res[:,0] + h[:,0]) ----------------
__global__ void __launch_bounds__(256) final_k(
    const float* __restrict__ res, const float* __restrict__ h,
    const float* __restrict__ fw, const float* __restrict__ fb, float* __restrict__ out)
{
    int b = blockIdx.x; int tid = threadIdx.x;
    const float* rr = res + (i64)(b*LTOK)*DM;
    const float* hr = h + (i64)(b*LTOK)*DM;
    float v[3]; float s = 0.f;
    #pragma unroll
    for (int i=0;i<3;i++){ int d = tid + i*256; v[i] = rr[d] + hr[d]; s += v[i]; }
    __shared__ float red[256];
    red[tid] = s; __syncthreads();
    for (int st=128; st>0; st>>=1){ if (tid < st) red[tid] += red[tid+st]; __syncthreads(); }
    float mean = red[0] / (float)DM;
    __syncthreads();
    float q = 0.f;
    #pragma unroll
    for (int i=0;i<3;i++){ float t = v[i]-mean; q += t*t; }
    red[tid] = q; __syncthreads();
    for (int st=128; st>0; st>>=1){ if (tid < st) red[tid] += red[tid+st]; __syncthreads(); }
    float iv = rsqrtf(red[0]/(float)DM + 1e-5f);
    #pragma unroll
    for (int i=0;i<3;i++){ int d = tid + i*256; out[b*DM + d] = (v[i]-mean)*iv*fw[d] + fb[d]; }
}

// ---------------- host ----------------
#define AP40 40
#define STG128 (128*AP40*2 + 128*AP40*2)
#define STG80  (128*AP40*2 + 80*AP40*2)
#define SMEM128_ ((3*STG128) > (128*132*4) ? (3*STG128) : (128*132*4))
#define SMEM80_  ((3*STG80)  > (128*84*4)  ? (3*STG80)  : (128*84*4))

extern "C" void kernel_launch(void* const* d_in, const int* in_sizes, int n_in,
                              void* d_out, int out_size)
{
    const float* x       = (const float*)d_in[0];
    const float* patch_w = (const float*)d_in[1];
    const float* patch_b = (const float*)d_in[2];
    const float* cls     = (const float*)d_in[3];
    const float* pos     = (const float*)d_in[4];
    const float* ln_w    = (const float*)d_in[5];
    const float* w_in    = (const float*)d_in[6];
    const float* conv_w  = (const float*)d_in[7];
    const float* conv_b  = (const float*)d_in[8];
    const float* w_x     = (const float*)d_in[9];
    const float* w_dt    = (const float*)d_in[10];
    const float* b_dt    = (const float*)d_in[11];
    const float* a_log   = (const float*)d_in[12];
    const float* dd      = (const float*)d_in[13];
    const float* w_out   = (const float*)d_in[14];
    const float* fn_w    = (const float*)d_in[15];
    const float* fn_b    = (const float*)d_in[16];

    float *h,*res,*xz,*c,*dblb,*dtb,*y;
    __nv_bfloat16 *winb,*wxb,*wdtb,*woutb,*pwb,*xnb,*cb,*dtAb,*ycb,*xpb;
    cudaGetSymbolAddress((void**)&h,    g_h);
    cudaGetSymbolAddress((void**)&res,  g_res);
    cudaGetSymbolAddress((void**)&xz,   g_xz);
    cudaGetSymbolAddress((void**)&c,    g_c);
    cudaGetSymbolAddress((void**)&dblb, g_dbl);
    cudaGetSymbolAddress((void**)&dtb,  g_dt);
    cudaGetSymbolAddress((void**)&y,    g_y);
    cudaGetSymbolAddress((void**)&winb, g_winb);
    cudaGetSymbolAddress((void**)&wxb,  g_wxb);
    cudaGetSymbolAddress((void**)&wdtb, g_wdtb);
    cudaGetSymbolAddress((void**)&woutb,g_woutb);
    cudaGetSymbolAddress((void**)&pwb,  g_pwb);
    cudaGetSymbolAddress((void**)&xnb,  g_xnb);
    cudaGetSymbolAddress((void**)&cb,   g_cb);
    cudaGetSymbolAddress((void**)&dtAb, g_dtAb);
    cudaGetSymbolAddress((void**)&ycb,  g_ycb);
    cudaGetSymbolAddress((void**)&xpb,  g_xpb);

    cudaFuncSetAttribute((const void*)mma_gemm_k<128,0>, cudaFuncAttributeMaxDynamicSharedMemorySize, SMEM128_);
    cudaFuncSetAttribute((const void*)mma_gemm_k<128,1>, cudaFuncAttributeMaxDynamicSharedMemorySize, SMEM128_);
    cudaFuncSetAttribute((const void*)mma_gemm_k<128,2>, cudaFuncAttributeMaxDynamicSharedMemorySize, SMEM128_);
    cudaFuncSetAttribute((const void*)mma_gemm_k<80,3>,  cudaFuncAttributeMaxDynamicSharedMemorySize, SMEM80_);

    // weight conversions (fp32 -> bf16 hi|lo)
    {
        i64 r1 = (i64)DEPTH*DX;      wconv_k<<<(int)((r1*DM  +255)/256),256>>>(w_in,  winb, DM,  DM,  r1);
        i64 r2 = (i64)DEPTH*2*DBLN;  wconv_k<<<(int)((r2*DI  +255)/256),256>>>(w_x,   wxb,  DI,  DI,  r2);
        i64 r3 = (i64)DEPTH*2*DI;    wconv_k<<<(int)((r3*64  +255)/256),256>>>(w_dt,  wdtb, DTR, 64,  r3);
        i64 r4 = (i64)DEPTH*DM;      wconv_k<<<(int)((r4*DI  +255)/256),256>>>(w_out, woutb,DI,  DI,  r4);
        i64 r5 = (i64)DM;            wconv_k<<<(int)((r5*PKK +255)/256),256>>>(patch_w,pwb, PKK, PKK, r5);
    }

    // patch embed
    gather_xp_k<<<(BATCH*NPATCH*PKK + 255)/256, 256>>>(x, xpb);
    cls_fill_k<<<(BATCH*DM + 255)/256, 256>>>(cls, pos, h);
    mma_gemm_k<128,1><<<dim3(DM/128, (BATCH*NPATCH)/128, 1), 256, SMEM128_>>>(
        xpb, pwb, h, BATCH*NPATCH, PKK, DM, 0,0,0, patch_b, 0, pos, nullptr, 0);

    const int MT_ = (ROWS + 127)/128;  // 17
    for (int l=0; l<DEPTH; l++){
        addrms_k<<<ROWS, 256>>>(res, h, xnb, ln_w + (i64)l*DM, l==0 ? 1 : 0);

        // xz = xn @ w_in^T  (2052 x 3072 x 768)
        mma_gemm_k<128,0><<<dim3(DX/128, MT_, 1), 256, SMEM128_>>>(
            xnb, winb + (i64)l*DX*2*DM, xz, ROWS, DM, DX,
            0,0,0, nullptr, 0, nullptr, nullptr, 0);

        conv_k<<<dim3(DI/256, LTOK, BATCH*2), 256>>>(
            xz, conv_w + (i64)l*2*DI*4, conv_b + (i64)l*2*DI, c, cb);

        // dbl = c @ w_x^T  (2052 x 80 x 1536, 2 dirs) + dtA aux
        mma_gemm_k<80,3><<<dim3(1, MT_, 2), 256, SMEM80_>>>(
            cb, wxb + (i64)l*2*DBLN*2*DI, dblb, ROWS, DI, DBLN,
            (i64)ROWS*2*DI, (i64)DBLN*2*DI, (i64)ROWS*DBLN,
            nullptr, 0, nullptr, dtAb, (i64)ROWS*128);

        // dt = softplus(dtA @ w_dt^T + b_dt)  (2052 x 1536 x 48, 2 dirs)
        mma_gemm_k<128,2><<<dim3(DI/128, MT_, 2), 256, SMEM128_>>>(
            dtAb, wdtb + (i64)l*2*DI*128, dtb, ROWS, 64, DI,
            (i64)ROWS*128, (i64)DI*128, (i64)ROWS*DI,
            b_dt + (i64)l*2*DI, (i64)DI, nullptr, nullptr, 0);

        scan_k<<<dim3(DI/256, BATCH, 2), 256>>>(
            c, dtb, dblb, xz, a_log + (i64)l*2*DI*DST, dd + (i64)l*2*DI, y);

        combine_k<<<(int)(((i64)ROWS*DI + 255)/256), 256>>>(y, ycb);

        // h = yc @ w_out^T  (2052 x 768 x 1536)
        mma_gemm_k<128,0><<<dim3(DM/128, MT_, 1), 256, SMEM128_>>>(
            ycb, woutb + (i64)l*DM*2*DI, h, ROWS, DI, DM,
            0,0,0, nullptr, 0, nullptr, nullptr, 0);
    }

    final_k<<<BATCH, 256>>>(res, h, fn_w, fn_b, (float*)d_out);
}

// round 5
// speedup vs baseline: 1.3854x; 1.1082x over previous
#include <cuda_runtime.h>
#include <cuda_bf16.h>

typedef unsigned int u32;
typedef unsigned long long u64;
typedef long long i64;

#define BATCH 4
#define LTOK 513
#define NPATCH 512
#define ROWS (BATCH*LTOK)
#define DM 768
#define DI 1536
#define DX 3072
#define DTR 48
#define DST 16
#define DBLN 80
#define DEPTH 24
#define PKK 256

// ---------------- fp32 scratch ----------------
__device__ __align__(256) float g_h  [ROWS*DM];
__device__ __align__(256) float g_res[ROWS*DM];
__device__ __align__(256) float g_xz [ROWS*DX];
__device__ __align__(256) float g_c  [2*ROWS*DI];
__device__ __align__(256) float g_dbl[2*ROWS*DBLN];
__device__ __align__(256) float g_dt [2*ROWS*DI];
__device__ __align__(256) float g_y  [2*ROWS*DI];

// ---------------- bf16 hi|lo split buffers (row = [hi(Kp) | lo(Kp)], pitch 2*Kp elems) ----------------
__device__ __align__(256) __nv_bfloat16 g_winb [DEPTH*DX*2*DM];
__device__ __align__(256) __nv_bfloat16 g_wxb  [DEPTH*2*DBLN*2*DI];
__device__ __align__(256) __nv_bfloat16 g_wdtb [DEPTH*2*DI*128];
__device__ __align__(256) __nv_bfloat16 g_woutb[DEPTH*DM*2*DI];
__device__ __align__(256) __nv_bfloat16 g_pwb  [DM*2*PKK];
__device__ __align__(256) __nv_bfloat16 g_xnb  [ROWS*2*DM];
__device__ __align__(256) __nv_bfloat16 g_cb   [2*ROWS*2*DI];
__device__ __align__(256) __nv_bfloat16 g_dtAb [2*ROWS*128];
__device__ __align__(256) __nv_bfloat16 g_ycb  [ROWS*2*DI];
__device__ __align__(256) __nv_bfloat16 g_xpb  [BATCH*NPATCH*2*PKK];

__device__ __forceinline__ float softplusf(float x){ return x > 20.f ? x : log1pf(__expf(x)); }
__device__ __forceinline__ float siluf(float x){ return x / (1.f + __expf(-x)); }

__device__ __forceinline__ u32 smem_u32(const void* p){
    u32 a; asm("{ .reg .u64 t; cvta.to.shared.u64 t, %1; cvt.u32.u64 %0, t; }" : "=r"(a) : "l"(p)); return a;
}
__device__ __forceinline__ void cpa16(u32 d, const void* g, int sz){
    asm volatile("cp.async.cg.shared.global [%0], [%1], 16, %2;" :: "r"(d), "l"(g), "r"(sz) : "memory");
}
__device__ __forceinline__ void ldm_x4(u32 a, u32& r0, u32& r1, u32& r2, u32& r3){
    asm volatile("ldmatrix.sync.aligned.m8n8.x4.shared.b16 {%0,%1,%2,%3}, [%4];"
        : "=r"(r0), "=r"(r1), "=r"(r2), "=r"(r3) : "r"(a));
}
__device__ __forceinline__ void mma16816(float* c, const u32* a, const u32* b){
    asm volatile("mma.sync.aligned.m16n8k16.row.col.f32.bf16.bf16.f32 "
        "{%0,%1,%2,%3}, {%4,%5,%6,%7}, {%8,%9}, {%0,%1,%2,%3};"
        : "+f"(c[0]),"+f"(c[1]),"+f"(c[2]),"+f"(c[3])
        : "r"(a[0]),"r"(a[1]),"r"(a[2]),"r"(a[3]),"r"(b[0]),"r"(b[1]));
}

// ==================== split-bf16 HMMA GEMM (merged-pass mainloop) ====================
// C[M,N] = A[M,K]*B[N,K]^T. Per 32-wide K chunk, load Ahi/Alo/Bhi/Blo once,
// issue 3 mma passes: Ahi*Bhi + Alo*Bhi + Ahi*Blo into fp32 accumulators.
// A,B rows: [hi(Kp) | lo(Kp)] bf16, pitch 4*Kp bytes. Kp % 32 == 0, N % TN == 0.
// MODE: 0=plain  1=patch(row remap+bias+pos)  2=softplus(+bias)  3=plain + dtA aux
template<int TN, int MODE>
__global__ void __launch_bounds__(256) mma_gemm_k(
    const __nv_bfloat16* __restrict__ A, const __nv_bfloat16* __restrict__ B,
    float* __restrict__ C, int M, int Kp, int ldc,
    i64 bsA, i64 bsB, i64 bsC,
    const float* __restrict__ bias, i64 bsBias,
    const float* __restrict__ pos,
    __nv_bfloat16* __restrict__ aux, i64 bsAux)
{
    constexpr int APB = 80;                    // bytes per 32-elem row (+8 elem pad)
    constexpr int AOFF_LO = 128*APB;
    constexpr int BOFF_HI = 2*128*APB;
    constexpr int BOFF_LO = BOFF_HI + TN*APB;
    constexpr int STG = BOFF_LO + TN*APB;      // per-slot bytes
    constexpr int WM = (TN >= 128) ? 4 : 8;
    constexpr int WN = 8 / WM;
    constexpr int RW = 128 / WM;
    constexpr int CW = TN / WN;
    constexpr int MT = RW / 16;
    constexpr int NT = CW / 8;
    constexpr int TP = TN + 4;

    extern __shared__ __align__(16) char smem[];
    const u32 sb = smem_u32(smem);
    const int tid = threadIdx.x;
    const int wid = tid >> 5;
    const int lane = tid & 31;
    const int wm = wid / WN, wn = wid % WN;
    const int m0 = blockIdx.y * 128;
    const int n0 = blockIdx.x * TN;
    A += (i64)blockIdx.z * bsA;
    B += (i64)blockIdx.z * bsB;
    C += (i64)blockIdx.z * bsC;
    if (bias) bias += (i64)blockIdx.z * bsBias;
    if (aux)  aux  += (i64)blockIdx.z * bsAux;

    const int KC = Kp / 32;
    const int KpB = Kp * 2;          // hi -> lo byte offset within a row
    const i64 pitch = 4*(i64)Kp;
    const char* Ab = (const char*)A;
    const char* Bb = (const char*)B;

    float acc[MT][NT][4];
    #pragma unroll
    for (int i=0;i<MT;i++)
        #pragma unroll
        for (int j=0;j<NT;j++)
            #pragma unroll
            for (int q=0;q<4;q++) acc[i][j][q] = 0.f;

    auto load_chunk = [&](int ci){
        int colB = ci*64;            // 32 bf16 = 64 bytes
        u32 s0 = sb + (ci & 1)*STG;
        #pragma unroll
        for (int s = tid; s < 128*4; s += 256){
            int row = s>>2, seg = s&3;
            int gm = m0 + row;
            int sz = (gm < M) ? 16 : 0;
            if (gm >= M) gm = 0;
            const char* bp = Ab + (i64)gm*pitch + colB + seg*16;
            cpa16(s0 + row*APB + seg*16, bp, sz);
            cpa16(s0 + AOFF_LO + row*APB + seg*16, bp + KpB, sz);
        }
        for (int s = tid; s < TN*4; s += 256){
            int row = s>>2, seg = s&3;
            const char* bp = Bb + (i64)(n0+row)*pitch + colB + seg*16;
            cpa16(s0 + BOFF_HI + row*APB + seg*16, bp, 16);
            cpa16(s0 + BOFF_LO + row*APB + seg*16, bp + KpB, 16);
        }
        asm volatile("cp.async.commit_group;" ::: "memory");
    };

    load_chunk(0);
    if (KC > 1) load_chunk(1);

    const int lr = lane & 7;
    const int q1 = (lane >> 3) & 1;
    const int q2 = (lane >> 4);

    for (int i = 0; i < KC; i++){
        if (i+1 < KC) asm volatile("cp.async.wait_group 1;" ::: "memory");
        else          asm volatile("cp.async.wait_group 0;" ::: "memory");
        __syncthreads();
        u32 s0 = sb + (i & 1)*STG;
        #pragma unroll
        for (int kk = 0; kk < 2; kk++){
            u32 ah[MT][4], al[MT][4], bf[NT][2];
            #pragma unroll
            for (int mt = 0; mt < MT; mt++){
                int row = wm*RW + mt*16 + lr + q1*8;
                int col2 = (kk*16 + q2*8)*2;
                ldm_x4(s0 + row*APB + col2, ah[mt][0],ah[mt][1],ah[mt][2],ah[mt][3]);
                ldm_x4(s0 + AOFF_LO + row*APB + col2, al[mt][0],al[mt][1],al[mt][2],al[mt][3]);
            }
            #pragma unroll
            for (int nt2 = 0; nt2 < NT/2; nt2++){
                int row = wn*CW + nt2*16 + q2*8 + lr;
                int col2 = (kk*16 + q1*8)*2;
                ldm_x4(s0 + BOFF_HI + row*APB + col2,
                       bf[2*nt2][0], bf[2*nt2][1], bf[2*nt2+1][0], bf[2*nt2+1][1]);
            }
            #pragma unroll
            for (int mt = 0; mt < MT; mt++)
                #pragma unroll
                for (int nt = 0; nt < NT; nt++)
                    mma16816(acc[mt][nt], ah[mt], bf[nt]);
            #pragma unroll
            for (int mt = 0; mt < MT; mt++)
                #pragma unroll
                for (int nt = 0; nt < NT; nt++)
                    mma16816(acc[mt][nt], al[mt], bf[nt]);
            #pragma unroll
            for (int nt2 = 0; nt2 < NT/2; nt2++){
                int row = wn*CW + nt2*16 + q2*8 + lr;
                int col2 = (kk*16 + q1*8)*2;
                ldm_x4(s0 + BOFF_LO + row*APB + col2,
                       bf[2*nt2][0], bf[2*nt2][1], bf[2*nt2+1][0], bf[2*nt2+1][1]);
            }
            #pragma unroll
            for (int mt = 0; mt < MT; mt++)
                #pragma unroll
                for (int nt = 0; nt < NT; nt++)
                    mma16816(acc[mt][nt], ah[mt], bf[nt]);
        }
        __syncthreads();
        if (i+2 < KC) load_chunk(i+2);
    }
    __syncthreads();

    // ---------- epilogue: accum -> smem tile -> coalesced gmem ----------
    float* tile = (float*)smem;   // [128][TP]
    {
        int rbase = wm*RW + (lane >> 2);
        int cbase = wn*CW + (lane & 3)*2;
        #pragma unroll
        for (int mt = 0; mt < MT; mt++){
            #pragma unroll
            for (int nt = 0; nt < NT; nt++){
                int r = rbase + mt*16;
                int cc = cbase + nt*8;
                tile[r*TP + cc]       = acc[mt][nt][0];
                tile[r*TP + cc + 1]   = acc[mt][nt][1];
                tile[(r+8)*TP + cc]   = acc[mt][nt][2];
                tile[(r+8)*TP + cc+1] = acc[mt][nt][3];
            }
        }
    }
    __syncthreads();

    constexpr int V4 = 128*(TN/4);
    for (int v = tid; v < V4; v += 256){
        int row = v / (TN/4);
        int col = (v % (TN/4)) * 4;
        int m = m0 + row;
        if (m >= M) continue;
        float4 val;
        val.x = tile[row*TP + col+0];
        val.y = tile[row*TP + col+1];
        val.z = tile[row*TP + col+2];
        val.w = tile[row*TP + col+3];
        int n = n0 + col;
        if (MODE == 1){
            int p = m & 511, b = m >> 9;
            i64 crow = (i64)(b*LTOK + p + 1)*ldc;
            const float* posr = pos + (i64)(p+1)*DM;
            val.x += bias[n+0] + posr[n+0];
            val.y += bias[n+1] + posr[n+1];
            val.z += bias[n+2] + posr[n+2];
            val.w += bias[n+3] + posr[n+3];
            *reinterpret_cast<float4*>(C + crow + n) = val;
        } else if (MODE == 2){
            val.x = softplusf(val.x + bias[n+0]);
            val.y = softplusf(val.y + bias[n+1]);
            val.z = softplusf(val.z + bias[n+2]);
            val.w = softplusf(val.w + bias[n+3]);
            *reinterpret_cast<float4*>(C + (i64)m*ldc + n) = val;
        } else {
            *reinterpret_cast<float4*>(C + (i64)m*ldc + n) = val;
        }
    }
    if (MODE == 3){
        for (int v = tid; v < 128*64; v += 256){
            int row = v >> 6, col = v & 63;
            int m = m0 + row;
            if (m >= M) continue;
            float x = (col < DTR) ? tile[row*TP + col] : 0.f;
            __nv_bfloat16 hi = __float2bfloat16(x);
            aux[(i64)m*128 + col]      = hi;
            aux[(i64)m*128 + 64 + col] = __float2bfloat16(x - __bfloat162float(hi));
        }
    }
}

// ---------------- merged weight conversion (single launch) ----------------
#define WC_N0 ((i64)DEPTH*DX*DM)        // w_in
#define WC_N1 ((i64)DEPTH*2*DBLN*DI)    // w_x
#define WC_N2 ((i64)DEPTH*2*DI*64)      // w_dt (Kp=64)
#define WC_N3 ((i64)DEPTH*DM*DI)        // w_out
#define WC_N4 ((i64)DM*PKK)             // patch_w
#define WC_TOT (WC_N0+WC_N1+WC_N2+WC_N3+WC_N4)

__global__ void wconv_all_k(const float* __restrict__ w_in, const float* __restrict__ w_x,
                            const float* __restrict__ w_dt, const float* __restrict__ w_out,
                            const float* __restrict__ patch_w,
                            __nv_bfloat16* __restrict__ winb, __nv_bfloat16* __restrict__ wxb,
                            __nv_bfloat16* __restrict__ wdtb, __nv_bfloat16* __restrict__ woutb,
                            __nv_bfloat16* __restrict__ pwb)
{
    i64 idx = (i64)blockIdx.x*256 + threadIdx.x;
    if (idx >= WC_TOT) return;
    const float* src; __nv_bfloat16* dst; int K, Kp;
    if (idx < WC_N0){ src=w_in; dst=winb; K=DM; Kp=DM; }
    else if ((idx -= WC_N0) < WC_N1){ src=w_x; dst=wxb; K=DI; Kp=DI; }
    else if ((idx -= WC_N1) < WC_N2){ src=w_dt; dst=wdtb; K=DTR; Kp=64; }
    else if ((idx -= WC_N2) < WC_N3){ src=w_out; dst=woutb; K=DI; Kp=DI; }
    else { idx -= WC_N3; src=patch_w; dst=pwb; K=PKK; Kp=PKK; }
    i64 n = idx / Kp; int k = (int)(idx - n*Kp);
    float v = (k < K) ? src[n*(i64)K + k] : 0.f;
    __nv_bfloat16 hi = __float2bfloat16(v);
    dst[n*(i64)(2*Kp) + k]      = hi;
    dst[n*(i64)(2*Kp) + Kp + k] = __float2bfloat16(v - __bfloat162float(hi));
}

// ---------------- patch gather + split ----------------
__global__ void gather_xp_k(const float* __restrict__ x, __nv_bfloat16* __restrict__ xpb){
    i64 idx = (i64)blockIdx.x*256 + threadIdx.x;
    if (idx >= (i64)BATCH*NPATCH*PKK) return;
    int k = (int)(idx & 255);
    int p = (int)((idx >> 8) & 511);
    int b = (int)(idx >> 17);
    int i = k >> 4, j = k & 15;
    int f = p >> 6, t = p & 63;
    float v = x[(i64)(b*128 + f*16 + i)*1024 + t*16 + j];
    __nv_bfloat16 hi = __float2bfloat16(v);
    i64 row = (i64)(b*NPATCH + p);
    xpb[row*512 + k]       = hi;
    xpb[row*512 + 256 + k] = __float2bfloat16(v - __bfloat162float(hi));
}

__global__ void cls_fill_k(const float* __restrict__ cls, const float* __restrict__ pos,
                           float* __restrict__ h){
    int idx = blockIdx.x*256 + threadIdx.x;
    if (idx >= BATCH*DM) return;
    int b = idx / DM, d = idx % DM;
    h[(i64)(b*LTOK)*DM + d] = cls[d] + pos[d];
}

// ---------------- res += h ; xnb = bf16split(rmsnorm(res)*lw) ----------------
__global__ void __launch_bounds__(256) addrms_k(
    float* __restrict__ res, const float* __restrict__ h, __nv_bfloat16* __restrict__ xnb,
    const float* __restrict__ lw, int first)
{
    int r = blockIdx.x;
    const float* hr = h + (i64)r*DM;
    float* rr = res + (i64)r*DM;
    __nv_bfloat16* xr = xnb + (i64)r*(2*DM);
    int tid = threadIdx.x;
    float v[3]; float ss = 0.f;
    #pragma unroll
    for (int i=0;i<3;i++){
        int d = tid + i*256;
        float t = first ? hr[d] : (rr[d] + hr[d]);
        v[i] = t; rr[d] = t; ss += t*t;
    }
    __shared__ float red[256];
    red[tid] = ss; __syncthreads();
    for (int s=128; s>0; s>>=1){ if (tid < s) red[tid] += red[tid+s]; __syncthreads(); }
    float scale = rsqrtf(red[0]/(float)DM + 1e-5f);
    #pragma unroll
    for (int i=0;i<3;i++){
        int d = tid + i*256;
        float o = v[i]*scale*lw[d];
        __nv_bfloat16 hi = __float2bfloat16(o);
        xr[d]      = hi;
        xr[DM + d] = __float2bfloat16(o - __bfloat162float(hi));
    }
}

// ---------------- causal conv + SiLU -> c (f32) + cb (bf16 split) ----------------
__global__ void conv_k(const float* __restrict__ xz, const float* __restrict__ cw,
                       const float* __restrict__ cb_, float* __restrict__ c,
                       __nv_bfloat16* __restrict__ cbb)
{
    int d = blockIdx.x*256 + threadIdx.x;
    int t = blockIdx.y;
    int z = blockIdx.z; int b = z >> 1; int dir = z & 1;
    const float* cwd = cw + (i64)(dir*DI + d)*4;
    float acc = cb_[dir*DI + d];
    #pragma unroll
    for (int k=0;k<4;k++){
        int tt = t - 3 + k;
        if (tt < 0) continue;
        int src = dir ? (NPATCH - tt) : tt;
        acc += xz[(i64)(b*LTOK + src)*DX + d] * cwd[k];
    }
    float o = siluf(acc);
    i64 row = (i64)(dir*ROWS + b*LTOK + t);
    c[row*DI + d] = o;
    __nv_bfloat16 hi = __float2bfloat16(o);
    cbb[row*(2*DI) + d]      = hi;
    cbb[row*(2*DI) + DI + d] = __float2bfloat16(o - __bfloat162float(hi));
}

// ---------------- sequential selective scan (128-thread blocks) ----------------
__global__ void __launch_bounds__(128) scan_k(
    const float* __restrict__ c, const float* __restrict__ dt,
    const float* __restrict__ dbl, const float* __restrict__ xz,
    const float* __restrict__ alog, const float* __restrict__ dd,
    float* __restrict__ y)
{
    int d = blockIdx.x*128 + threadIdx.x;
    int b = blockIdx.y, dir = blockIdx.z;
    const float LOG2E = 1.4426950408889634f;
    float A2[DST];
    #pragma unroll
    for (int s=0;s<DST;s++) A2[s] = -__expf(alog[(i64)(dir*DI + d)*DST + s]) * LOG2E;
    float Dv = dd[dir*DI + d];
    float h[DST];
    #pragma unroll
    for (int s=0;s<DST;s++) h[s] = 0.f;

    i64 base = (i64)(dir*ROWS + b*LTOK)*DI + d;
    const float* dblp = dbl + (i64)(dir*ROWS + b*LTOK)*DBLN;
    const float* zp = xz + (i64)(b*LTOK)*DX + DI + d;

    for (int t=0;t<LTOK;t++){
        float dtv = dt[base + (i64)t*DI];
        float cv  = c [base + (i64)t*DI];
        const float4* br = reinterpret_cast<const float4*>(dblp + t*DBLN + DTR);
        float Bv[DST], Cv[DST];
        *reinterpret_cast<float4*>(&Bv[0])  = br[0];
        *reinterpret_cast<float4*>(&Bv[4])  = br[1];
        *reinterpret_cast<float4*>(&Bv[8])  = br[2];
        *reinterpret_cast<float4*>(&Bv[12]) = br[3];
        *reinterpret_cast<float4*>(&Cv[0])  = br[4];
        *reinterpret_cast<float4*>(&Cv[4])  = br[5];
        *reinterpret_cast<float4*>(&Cv[8])  = br[6];
        *reinterpret_cast<float4*>(&Cv[12]) = br[7];
        float du = dtv * cv;
        float y0=0.f, y1=0.f, y2=0.f, y3=0.f;
        #pragma unroll
        for (int s=0;s<DST;s+=4){
            float dA0 = exp2f(dtv*A2[s+0]);
            float dA1 = exp2f(dtv*A2[s+1]);
            float dA2_ = exp2f(dtv*A2[s+2]);
            float dA3 = exp2f(dtv*A2[s+3]);
            h[s+0] = dA0*h[s+0] + du*Bv[s+0];
            h[s+1] = dA1*h[s+1] + du*Bv[s+1];
            h[s+2] = dA2_*h[s+2] + du*Bv[s+2];
            h[s+3] = dA3*h[s+3] + du*Bv[s+3];
            y0 += h[s+0]*Cv[s+0];
            y1 += h[s+1]*Cv[s+1];
            y2 += h[s+2]*Cv[s+2];
            y3 += h[s+3]*Cv[s+3];
        }
        float yv = (y0+y1)+(y2+y3) + cv*Dv;
        int zt = dir ? (NPATCH - t) : t;
        float zv = zp[(i64)zt*DX];
        yv *= siluf(zv);
        y[base + (i64)t*DI] = yv;
    }
}

// ---------------- combine -> ycb (bf16 split) ----------------
__global__ void combine_k(const float* __restrict__ y, __nv_bfloat16* __restrict__ ycb){
    i64 idx = (i64)blockIdx.x*256 + threadIdx.x;
    if (idx >= (i64)ROWS*DI) return;
    int d = (int)(idx % DI);
    i64 row = idx / DI;
    int b = (int)(row / LTOK); int t = (int)(row % LTOK);
    float a = y[idx];
    float bb = y[(i64)(ROWS + b*LTOK + (NPATCH - t))*DI + d];
    float o = 0.5f*(a + bb);
    __nv_bfloat16 hi = __float2bfloat16(o);
    ycb[row*(2*DI) + d]      = hi;
    ycb[row*(2*DI) + DI + d] = __float2bfloat16(o - __bfloat162float(hi));
}

// ---------------- final layer_norm(res[:,0] + h[:,0]) ----------------
__global__ void __launch_bounds__(256) final_k(
    const float* __restrict__ res, const float* __restrict__ h,
    const float* __restrict__ fw, const float* __restrict__ fb, float* __restrict__ out)
{
    int b = blockIdx.x; int tid = threadIdx.x;
    const float* rr = res + (i64)(b*LTOK)*DM;
    const float* hr = h + (i64)(b*LTOK)*DM;
    float v[3]; float s = 0.f;
    #pragma unroll
    for (int i=0;i<3;i++){ int d = tid + i*256; v[i] = rr[d] + hr[d]; s += v[i]; }
    __shared__ float red[256];
    red[tid] = s; __syncthreads();
    for (int st=128; st>0; st>>=1){ if (tid < st) red[tid] += red[tid+st]; __syncthreads(); }
    float mean = red[0] / (float)DM;
    __syncthreads();
    float q = 0.f;
    #pragma unroll
    for (int i=0;i<3;i++){ float t = v[i]-mean; q += t*t; }
    red[tid] = q; __syncthreads();
    for (int st=128; st>0; st>>=1){ if (tid < st) red[tid] += red[tid+st]; __syncthreads(); }
    float iv = rsqrtf(red[0]/(float)DM + 1e-5f);
    #pragma unroll
    for (int i=0;i<3;i++){ int d = tid + i*256; out[b*DM + d] = (v[i]-mean)*iv*fw[d] + fb[d]; }
}

// ---------------- host ----------------
#define STGB(TN) (2*128*80 + 2*(TN)*80)
#define EPIB(TN) (128*((TN)+4)*4)
#define SMEM128_ ((2*STGB(128)) > EPIB(128) ? (2*STGB(128)) : EPIB(128))
#define SMEM80_  ((2*STGB(80))  > EPIB(80)  ? (2*STGB(80))  : EPIB(80))

extern "C" void kernel_launch(void* const* d_in, const int* in_sizes, int n_in,
                              void* d_out, int out_size)
{
    const float* x       = (const float*)d_in[0];
    const float* patch_w = (const float*)d_in[1];
    const float* patch_b = (const float*)d_in[2];
    const float* cls     = (const float*)d_in[3];
    const float* pos     = (const float*)d_in[4];
    const float* ln_w    = (const float*)d_in[5];
    const float* w_in    = (const float*)d_in[6];
    const float* conv_w  = (const float*)d_in[7];
    const float* conv_b  = (const float*)d_in[8];
    const float* w_x     = (const float*)d_in[9];
    const float* w_dt    = (const float*)d_in[10];
    const float* b_dt    = (const float*)d_in[11];
    const float* a_log   = (const float*)d_in[12];
    const float* dd      = (const float*)d_in[13];
    const float* w_out   = (const float*)d_in[14];
    const float* fn_w    = (const float*)d_in[15];
    const float* fn_b    = (const float*)d_in[16];

    float *h,*res,*xz,*c,*dblb,*dtb,*y;
    __nv_bfloat16 *winb,*wxb,*wdtb,*woutb,*pwb,*xnb,*cb,*dtAb,*ycb,*xpb;
    cudaGetSymbolAddress((void**)&h,    g_h);
    cudaGetSymbolAddress((void**)&res,  g_res);
    cudaGetSymbolAddress((void**)&xz,   g_xz);
    cudaGetSymbolAddress((void**)&c,    g_c);
    cudaGetSymbolAddress((void**)&dblb, g_dbl);
    cudaGetSymbolAddress((void**)&dtb,  g_dt);
    cudaGetSymbolAddress((void**)&y,    g_y);
    cudaGetSymbolAddress((void**)&winb, g_winb);
    cudaGetSymbolAddress((void**)&wxb,  g_wxb);
    cudaGetSymbolAddress((void**)&wdtb, g_wdtb);
    cudaGetSymbolAddress((void**)&woutb,g_woutb);
    cudaGetSymbolAddress((void**)&pwb,  g_pwb);
    cudaGetSymbolAddress((void**)&xnb,  g_xnb);
    cudaGetSymbolAddress((void**)&cb,   g_cb);
    cudaGetSymbolAddress((void**)&dtAb, g_dtAb);
    cudaGetSymbolAddress((void**)&ycb,  g_ycb);
    cudaGetSymbolAddress((void**)&xpb,  g_xpb);

    cudaFuncSetAttribute((const void*)mma_gemm_k<128,0>, cudaFuncAttributeMaxDynamicSharedMemorySize, SMEM128_);
    cudaFuncSetAttribute((const void*)mma_gemm_k<128,1>, cudaFuncAttributeMaxDynamicSharedMemorySize, SMEM128_);
    cudaFuncSetAttribute((const void*)mma_gemm_k<128,2>, cudaFuncAttributeMaxDynamicSharedMemorySize, SMEM128_);
    cudaFuncSetAttribute((const void*)mma_gemm_k<80,3>,  cudaFuncAttributeMaxDynamicSharedMemorySize, SMEM80_);

    // launch 0: merged weight conversion
    wconv_all_k<<<(int)((WC_TOT + 255)/256), 256>>>(w_in, w_x, w_dt, w_out, patch_w,
                                                    winb, wxb, wdtb, woutb, pwb);
    // launches 1-3
    gather_xp_k<<<(BATCH*NPATCH*PKK + 255)/256, 256>>>(x, xpb);
    cls_fill_k<<<(BATCH*DM + 255)/256, 256>>>(cls, pos, h);
    mma_gemm_k<128,1><<<dim3(DM/128, (BATCH*NPATCH)/128, 1), 256, SMEM128_>>>(
        xpb, pwb, h, BATCH*NPATCH, PKK, DM, 0,0,0, patch_b, 0, pos, nullptr, 0);

    const int MT_ = (ROWS + 127)/128;  // 17
    for (int l=0; l<DEPTH; l++){
        // launch 4 (layer 0)
        addrms_k<<<ROWS, 256>>>(res, h, xnb, ln_w + (i64)l*DM, l==0 ? 1 : 0);

        // launch 5 (layer 0) = profiled by ncu: xz = xn @ w_in^T  (2052 x 3072 x 768)
        mma_gemm_k<128,0><<<dim3(DX/128, MT_, 1), 256, SMEM128_>>>(
            xnb, winb + (i64)l*DX*2*DM, xz, ROWS, DM, DX,
            0,0,0, nullptr, 0, nullptr, nullptr, 0);

        conv_k<<<dim3(DI/256, LTOK, BATCH*2), 256>>>(
            xz, conv_w + (i64)l*2*DI*4, conv_b + (i64)l*2*DI, c, cb);

        // dbl = c @ w_x^T  (2052 x 80 x 1536, 2 dirs) + dtA aux
        mma_gemm_k<80,3><<<dim3(1, MT_, 2), 256, SMEM80_>>>(
            cb, wxb + (i64)l*2*DBLN*2*DI, dblb, ROWS, DI, DBLN,
            (i64)ROWS*2*DI, (i64)DBLN*2*DI, (i64)ROWS*DBLN,
            nullptr, 0, nullptr, dtAb, (i64)ROWS*128);

        // dt = softplus(dtA @ w_dt^T + b_dt)  (2052 x 1536 x 48, 2 dirs)
        mma_gemm_k<128,2><<<dim3(DI/128, MT_, 2), 256, SMEM128_>>>(
            dtAb, wdtb + (i64)l*2*DI*128, dtb, ROWS, 64, DI,
            (i64)ROWS*128, (i64)DI*128, (i64)ROWS*DI,
            b_dt + (i64)l*2*DI, (i64)DI, nullptr, nullptr, 0);

        scan_k<<<dim3(DI/128, BATCH, 2), 128>>>(
            c, dtb, dblb, xz, a_log + (i64)l*2*DI*DST, dd + (i64)l*2*DI, y);

        combine_k<<<(int)(((i64)ROWS*DI + 255)/256), 256>>>(y, ycb);

        // h = yc @ w_out^T  (2052 x 768 x 1536)
        mma_gemm_k<128,0><<<dim3(DM/128, MT_, 1), 256, SMEM128_>>>(
            ycb, woutb + (i64)l*DM*2*DI, h, ROWS, DI, DM,
            0,0,0, nullptr, 0, nullptr, nullptr, 0);
    }

    final_k<<<BATCH, 256>>>(res, h, fn_w, fn_b, (float*)d_out);
}

// round 6
// speedup vs baseline: 1.4077x; 1.0161x over previous
#include <cuda_runtime.h>
#include <cuda_bf16.h>

typedef unsigned int u32;
typedef unsigned long long u64;
typedef long long i64;

#define BATCH 4
#define LTOK 513
#define NPATCH 512
#define ROWS (BATCH*LTOK)
#define DM 768
#define DI 1536
#define DX 3072
#define DTR 48
#define DST 16
#define DBLN 80
#define DEPTH 24
#define PKK 256

// ---------------- fp32 scratch ----------------
__device__ __align__(256) float g_h  [ROWS*DM];
__device__ __align__(256) float g_res[ROWS*DM];
__device__ __align__(256) float g_xz [ROWS*DX];
__device__ __align__(256) float g_c  [2*ROWS*DI];
__device__ __align__(256) float g_dbl[2*ROWS*DBLN];
__device__ __align__(256) float g_dt [2*ROWS*DI];
__device__ __align__(256) float g_y  [2*ROWS*DI];

// ---------------- bf16 hi|lo split buffers (row = [hi(Kp) | lo(Kp)], pitch 2*Kp elems) ----------------
__device__ __align__(256) __nv_bfloat16 g_winb [DEPTH*DX*2*DM];
__device__ __align__(256) __nv_bfloat16 g_wxb  [DEPTH*2*DBLN*2*DI];
__device__ __align__(256) __nv_bfloat16 g_wdtb [DEPTH*2*DI*128];
__device__ __align__(256) __nv_bfloat16 g_woutb[DEPTH*DM*2*DI];
__device__ __align__(256) __nv_bfloat16 g_pwb  [DM*2*PKK];
__device__ __align__(256) __nv_bfloat16 g_xnb  [ROWS*2*DM];
__device__ __align__(256) __nv_bfloat16 g_cb   [2*ROWS*2*DI];
__device__ __align__(256) __nv_bfloat16 g_dtAb [2*ROWS*128];
__device__ __align__(256) __nv_bfloat16 g_ycb  [ROWS*2*DI];
__device__ __align__(256) __nv_bfloat16 g_xpb  [BATCH*NPATCH*2*PKK];

__device__ __forceinline__ float softplusf(float x){ return x > 20.f ? x : log1pf(__expf(x)); }
__device__ __forceinline__ float siluf(float x){ return x / (1.f + __expf(-x)); }

__device__ __forceinline__ u32 smem_u32(const void* p){
    u32 a; asm("{ .reg .u64 t; cvta.to.shared.u64 t, %1; cvt.u32.u64 %0, t; }" : "=r"(a) : "l"(p)); return a;
}
__device__ __forceinline__ void cpa16(u32 d, const void* g, int sz){
    asm volatile("cp.async.cg.shared.global [%0], [%1], 16, %2;" :: "r"(d), "l"(g), "r"(sz) : "memory");
}
__device__ __forceinline__ void ldm_x4(u32 a, u32& r0, u32& r1, u32& r2, u32& r3){
    asm volatile("ldmatrix.sync.aligned.m8n8.x4.shared.b16 {%0,%1,%2,%3}, [%4];"
        : "=r"(r0), "=r"(r1), "=r"(r2), "=r"(r3) : "r"(a));
}
__device__ __forceinline__ void mma16816(float* c, const u32* a, const u32* b){
    asm volatile("mma.sync.aligned.m16n8k16.row.col.f32.bf16.bf16.f32 "
        "{%0,%1,%2,%3}, {%4,%5,%6,%7}, {%8,%9}, {%0,%1,%2,%3};"
        : "+f"(c[0]),"+f"(c[1]),"+f"(c[2]),"+f"(c[3])
        : "r"(a[0]),"r"(a[1]),"r"(a[2]),"r"(a[3]),"r"(b[0]),"r"(b[1]));
}

// ==================== split-bf16 HMMA GEMM (merged-pass, 2 CTA/SM) ====================
// C[M,N] = A[M,K]*B[N,K]^T. Per 32-wide K chunk, load Ahi/Alo/Bhi/Blo once,
// 3 mma passes: Ahi*Bhi + Alo*Bhi + Ahi*Blo into fp32 accumulators.
// A,B rows: [hi(Kp) | lo(Kp)] bf16, pitch 4*Kp bytes. Kp % 32 == 0, N % TN == 0.
// MODE: 0=plain  1=patch(row remap+bias+pos)  2=softplus(+bias)  3=plain + dtA aux
template<int TN, int MODE>
__global__ void __launch_bounds__(256,2) mma_gemm_k(
    const __nv_bfloat16* __restrict__ A, const __nv_bfloat16* __restrict__ B,
    float* __restrict__ C, int M, int Kp, int ldc,
    i64 bsA, i64 bsB, i64 bsC,
    const float* __restrict__ bias, i64 bsBias,
    const float* __restrict__ pos,
    __nv_bfloat16* __restrict__ aux, i64 bsAux)
{
    constexpr int APB = 80;                    // bytes per 32-elem row (+8 elem pad)
    constexpr int AOFF_LO = 128*APB;
    constexpr int BOFF_HI = 2*128*APB;
    constexpr int BOFF_LO = BOFF_HI + TN*APB;
    constexpr int STG = BOFF_LO + TN*APB;      // per-slot bytes
    constexpr int WM = (TN >= 128) ? 4 : 8;
    constexpr int WN = 8 / WM;
    constexpr int RW = 128 / WM;
    constexpr int CW = TN / WN;
    constexpr int MT = RW / 16;
    constexpr int NT = CW / 8;
    constexpr int TP = TN + 4;

    extern __shared__ __align__(16) char smem[];
    const u32 sb = smem_u32(smem);
    const int tid = threadIdx.x;
    const int wid = tid >> 5;
    const int lane = tid & 31;
    const int wm = wid / WN, wn = wid % WN;
    const int m0 = blockIdx.y * 128;
    const int n0 = blockIdx.x * TN;
    A += (i64)blockIdx.z * bsA;
    B += (i64)blockIdx.z * bsB;
    C += (i64)blockIdx.z * bsC;
    if (bias) bias += (i64)blockIdx.z * bsBias;
    if (aux)  aux  += (i64)blockIdx.z * bsAux;

    const int KC = Kp / 32;
    const int KpB = Kp * 2;          // hi -> lo byte offset within a row
    const i64 pitch = 4*(i64)Kp;
    const char* Ab = (const char*)A;
    const char* Bb = (const char*)B;

    float acc[MT][NT][4];
    #pragma unroll
    for (int i=0;i<MT;i++)
        #pragma unroll
        for (int j=0;j<NT;j++)
            #pragma unroll
            for (int q=0;q<4;q++) acc[i][j][q] = 0.f;

    auto load_chunk = [&](int ci){
        int colB = ci*64;            // 32 bf16 = 64 bytes
        u32 s0 = sb + (ci & 1)*STG;
        #pragma unroll
        for (int s = tid; s < 128*4; s += 256){
            int row = s>>2, seg = s&3;
            int gm = m0 + row;
            int sz = (gm < M) ? 16 : 0;
            if (gm >= M) gm = 0;
            const char* bp = Ab + (i64)gm*pitch + colB + seg*16;
            cpa16(s0 + row*APB + seg*16, bp, sz);
            cpa16(s0 + AOFF_LO + row*APB + seg*16, bp + KpB, sz);
        }
        for (int s = tid; s < TN*4; s += 256){
            int row = s>>2, seg = s&3;
            const char* bp = Bb + (i64)(n0+row)*pitch + colB + seg*16;
            cpa16(s0 + BOFF_HI + row*APB + seg*16, bp, 16);
            cpa16(s0 + BOFF_LO + row*APB + seg*16, bp + KpB, 16);
        }
        asm volatile("cp.async.commit_group;" ::: "memory");
    };

    load_chunk(0);
    if (KC > 1) load_chunk(1);

    // hoisted ldmatrix base offsets (byte offsets within a slot)
    const int lr = lane & 7;
    const int q1 = (lane >> 3) & 1;
    const int q2 = (lane >> 4);
    u32 aRowOff[MT];     // A: row = wm*RW + mt*16 + lr + q1*8, col base q2*8
    #pragma unroll
    for (int mt = 0; mt < MT; mt++)
        aRowOff[mt] = (u32)((wm*RW + mt*16 + lr + q1*8)*APB + q2*8*2);
    u32 bRowOff[NT/2];   // B: row = wn*CW + nt2*16 + q2*8 + lr, col base q1*8
    #pragma unroll
    for (int nt2 = 0; nt2 < NT/2; nt2++)
        bRowOff[nt2] = (u32)((wn*CW + nt2*16 + q2*8 + lr)*APB + q1*8*2);

    for (int i = 0; i < KC; i++){
        if (i+1 < KC) asm volatile("cp.async.wait_group 1;" ::: "memory");
        else          asm volatile("cp.async.wait_group 0;" ::: "memory");
        __syncthreads();
        u32 s0 = sb + (i & 1)*STG;
        #pragma unroll
        for (int kk = 0; kk < 2; kk++){
            u32 cOff = (u32)(kk*32);   // kk*16 elems * 2 bytes
            u32 ah[MT][4], al[MT][4], bf[NT][2];
            #pragma unroll
            for (int mt = 0; mt < MT; mt++){
                ldm_x4(s0 + aRowOff[mt] + cOff, ah[mt][0],ah[mt][1],ah[mt][2],ah[mt][3]);
                ldm_x4(s0 + AOFF_LO + aRowOff[mt] + cOff, al[mt][0],al[mt][1],al[mt][2],al[mt][3]);
            }
            #pragma unroll
            for (int nt2 = 0; nt2 < NT/2; nt2++)
                ldm_x4(s0 + BOFF_HI + bRowOff[nt2] + cOff,
                       bf[2*nt2][0], bf[2*nt2][1], bf[2*nt2+1][0], bf[2*nt2+1][1]);
            #pragma unroll
            for (int mt = 0; mt < MT; mt++)
                #pragma unroll
                for (int nt = 0; nt < NT; nt++)
                    mma16816(acc[mt][nt], ah[mt], bf[nt]);
            #pragma unroll
            for (int mt = 0; mt < MT; mt++)
                #pragma unroll
                for (int nt = 0; nt < NT; nt++)
                    mma16816(acc[mt][nt], al[mt], bf[nt]);
            #pragma unroll
            for (int nt2 = 0; nt2 < NT/2; nt2++)
                ldm_x4(s0 + BOFF_LO + bRowOff[nt2] + cOff,
                       bf[2*nt2][0], bf[2*nt2][1], bf[2*nt2+1][0], bf[2*nt2+1][1]);
            #pragma unroll
            for (int mt = 0; mt < MT; mt++)
                #pragma unroll
                for (int nt = 0; nt < NT; nt++)
                    mma16816(acc[mt][nt], ah[mt], bf[nt]);
        }
        __syncthreads();
        if (i+2 < KC) load_chunk(i+2);
    }
    __syncthreads();

    // ---------- epilogue: accum -> smem tile -> coalesced gmem ----------
    float* tile = (float*)smem;   // [128][TP]
    {
        int rbase = wm*RW + (lane >> 2);
        int cbase = wn*CW + (lane & 3)*2;
        #pragma unroll
        for (int mt = 0; mt < MT; mt++){
            #pragma unroll
            for (int nt = 0; nt < NT; nt++){
                int r = rbase + mt*16;
                int cc = cbase + nt*8;
                tile[r*TP + cc]       = acc[mt][nt][0];
                tile[r*TP + cc + 1]   = acc[mt][nt][1];
                tile[(r+8)*TP + cc]   = acc[mt][nt][2];
                tile[(r+8)*TP + cc+1] = acc[mt][nt][3];
            }
        }
    }
    __syncthreads();

    constexpr int V4 = 128*(TN/4);
    for (int v = tid; v < V4; v += 256){
        int row = v / (TN/4);
        int col = (v % (TN/4)) * 4;
        int m = m0 + row;
        if (m >= M) continue;
        float4 val;
        val.x = tile[row*TP + col+0];
        val.y = tile[row*TP + col+1];
        val.z = tile[row*TP + col+2];
        val.w = tile[row*TP + col+3];
        int n = n0 + col;
        if (MODE == 1){
            int p = m & 511, b = m >> 9;
            i64 crow = (i64)(b*LTOK + p + 1)*ldc;
            const float* posr = pos + (i64)(p+1)*DM;
            val.x += bias[n+0] + posr[n+0];
            val.y += bias[n+1] + posr[n+1];
            val.z += bias[n+2] + posr[n+2];
            val.w += bias[n+3] + posr[n+3];
            *reinterpret_cast<float4*>(C + crow + n) = val;
        } else if (MODE == 2){
            val.x = softplusf(val.x + bias[n+0]);
            val.y = softplusf(val.y + bias[n+1]);
            val.z = softplusf(val.z + bias[n+2]);
            val.w = softplusf(val.w + bias[n+3]);
            *reinterpret_cast<float4*>(C + (i64)m*ldc + n) = val;
        } else {
            *reinterpret_cast<float4*>(C + (i64)m*ldc + n) = val;
        }
    }
    if (MODE == 3){
        for (int v = tid; v < 128*64; v += 256){
            int row = v >> 6, col = v & 63;
            int m = m0 + row;
            if (m >= M) continue;
            float x = (col < DTR) ? tile[row*TP + col] : 0.f;
            __nv_bfloat16 hi = __float2bfloat16(x);
            aux[(i64)m*128 + col]      = hi;
            aux[(i64)m*128 + 64 + col] = __float2bfloat16(x - __bfloat162float(hi));
        }
    }
}

// ---------------- merged weight conversion (single launch) ----------------
#define WC_N0 ((i64)DEPTH*DX*DM)        // w_in
#define WC_N1 ((i64)DEPTH*2*DBLN*DI)    // w_x
#define WC_N2 ((i64)DEPTH*2*DI*64)      // w_dt (Kp=64)
#define WC_N3 ((i64)DEPTH*DM*DI)        // w_out
#define WC_N4 ((i64)DM*PKK)             // patch_w
#define WC_TOT (WC_N0+WC_N1+WC_N2+WC_N3+WC_N4)

__global__ void wconv_all_k(const float* __restrict__ w_in, const float* __restrict__ w_x,
                            const float* __restrict__ w_dt, const float* __restrict__ w_out,
                            const float* __restrict__ patch_w,
                            __nv_bfloat16* __restrict__ winb, __nv_bfloat16* __restrict__ wxb,
                            __nv_bfloat16* __restrict__ wdtb, __nv_bfloat16* __restrict__ woutb,
                            __nv_bfloat16* __restrict__ pwb)
{
    i64 idx = (i64)blockIdx.x*256 + threadIdx.x;
    if (idx >= WC_TOT) return;
    const float* src; __nv_bfloat16* dst; int K, Kp;
    if (idx < WC_N0){ src=w_in; dst=winb; K=DM; Kp=DM; }
    else if ((idx -= WC_N0) < WC_N1){ src=w_x; dst=wxb; K=DI; Kp=DI; }
    else if ((idx -= WC_N1) < WC_N2){ src=w_dt; dst=wdtb; K=DTR; Kp=64; }
    else if ((idx -= WC_N2) < WC_N3){ src=w_out; dst=woutb; K=DI; Kp=DI; }
    else { idx -= WC_N3; src=patch_w; dst=pwb; K=PKK; Kp=PKK; }
    i64 n = idx / Kp; int k = (int)(idx - n*Kp);
    float v = (k < K) ? src[n*(i64)K + k] : 0.f;
    __nv_bfloat16 hi = __float2bfloat16(v);
    dst[n*(i64)(2*Kp) + k]      = hi;
    dst[n*(i64)(2*Kp) + Kp + k] = __float2bfloat16(v - __bfloat162float(hi));
}

// ---------------- patch gather + split ----------------
__global__ void gather_xp_k(const float* __restrict__ x, __nv_bfloat16* __restrict__ xpb){
    i64 idx = (i64)blockIdx.x*256 + threadIdx.x;
    if (idx >= (i64)BATCH*NPATCH*PKK) return;
    int k = (int)(idx & 255);
    int p = (int)((idx >> 8) & 511);
    int b = (int)(idx >> 17);
    int i = k >> 4, j = k & 15;
    int f = p >> 6, t = p & 63;
    float v = x[(i64)(b*128 + f*16 + i)*1024 + t*16 + j];
    __nv_bfloat16 hi = __float2bfloat16(v);
    i64 row = (i64)(b*NPATCH + p);
    xpb[row*512 + k]       = hi;
    xpb[row*512 + 256 + k] = __float2bfloat16(v - __bfloat162float(hi));
}

__global__ void cls_fill_k(const float* __restrict__ cls, const float* __restrict__ pos,
                           float* __restrict__ h){
    int idx = blockIdx.x*256 + threadIdx.x;
    if (idx >= BATCH*DM) return;
    int b = idx / DM, d = idx % DM;
    h[(i64)(b*LTOK)*DM + d] = cls[d] + pos[d];
}

// ---------------- res += h ; xnb = bf16split(rmsnorm(res)*lw) ----------------
__global__ void __launch_bounds__(256) addrms_k(
    float* __restrict__ res, const float* __restrict__ h, __nv_bfloat16* __restrict__ xnb,
    const float* __restrict__ lw, int first)
{
    int r = blockIdx.x;
    const float* hr = h + (i64)r*DM;
    float* rr = res + (i64)r*DM;
    __nv_bfloat16* xr = xnb + (i64)r*(2*DM);
    int tid = threadIdx.x;
    float v[3]; float ss = 0.f;
    #pragma unroll
    for (int i=0;i<3;i++){
        int d = tid + i*256;
        float t = first ? hr[d] : (rr[d] + hr[d]);
        v[i] = t; rr[d] = t; ss += t*t;
    }
    __shared__ float red[256];
    red[tid] = ss; __syncthreads();
    for (int s=128; s>0; s>>=1){ if (tid < s) red[tid] += red[tid+s]; __syncthreads(); }
    float scale = rsqrtf(red[0]/(float)DM + 1e-5f);
    #pragma unroll
    for (int i=0;i<3;i++){
        int d = tid + i*256;
        float o = v[i]*scale*lw[d];
        __nv_bfloat16 hi = __float2bfloat16(o);
        xr[d]      = hi;
        xr[DM + d] = __float2bfloat16(o - __bfloat162float(hi));
    }
}

// ---------------- causal conv + SiLU -> c (f32) + cb (bf16 split) ----------------
__global__ void conv_k(const float* __restrict__ xz, const float* __restrict__ cw,
                       const float* __restrict__ cb_, float* __restrict__ c,
                       __nv_bfloat16* __restrict__ cbb)
{
    int d = blockIdx.x*256 + threadIdx.x;
    int t = blockIdx.y;
    int z = blockIdx.z; int b = z >> 1; int dir = z & 1;
    const float* cwd = cw + (i64)(dir*DI + d)*4;
    float acc = cb_[dir*DI + d];
    #pragma unroll
    for (int k=0;k<4;k++){
        int tt = t - 3 + k;
        if (tt < 0) continue;
        int src = dir ? (NPATCH - tt) : tt;
        acc += xz[(i64)(b*LTOK + src)*DX + d] * cwd[k];
    }
    float o = siluf(acc);
    i64 row = (i64)(dir*ROWS + b*LTOK + t);
    c[row*DI + d] = o;
    __nv_bfloat16 hi = __float2bfloat16(o);
    cbb[row*(2*DI) + d]      = hi;
    cbb[row*(2*DI) + DI + d] = __float2bfloat16(o - __bfloat162float(hi));
}

// ---------------- sequential selective scan (128-thread blocks) ----------------
__global__ void __launch_bounds__(128) scan_k(
    const float* __restrict__ c, const float* __restrict__ dt,
    const float* __restrict__ dbl, const float* __restrict__ xz,
    const float* __restrict__ alog, const float* __restrict__ dd,
    float* __restrict__ y)
{
    int d = blockIdx.x*128 + threadIdx.x;
    int b = blockIdx.y, dir = blockIdx.z;
    const float LOG2E = 1.4426950408889634f;
    float A2[DST];
    #pragma unroll
    for (int s=0;s<DST;s++) A2[s] = -__expf(alog[(i64)(dir*DI + d)*DST + s]) * LOG2E;
    float Dv = dd[dir*DI + d];
    float h[DST];
    #pragma unroll
    for (int s=0;s<DST;s++) h[s] = 0.f;

    i64 base = (i64)(dir*ROWS + b*LTOK)*DI + d;
    const float* dblp = dbl + (i64)(dir*ROWS + b*LTOK)*DBLN;
    const float* zp = xz + (i64)(b*LTOK)*DX + DI + d;

    for (int t=0;t<LTOK;t++){
        float dtv = dt[base + (i64)t*DI];
        float cv  = c [base + (i64)t*DI];
        const float4* br = reinterpret_cast<const float4*>(dblp + t*DBLN + DTR);
        float Bv[DST], Cv[DST];
        *reinterpret_cast<float4*>(&Bv[0])  = br[0];
        *reinterpret_cast<float4*>(&Bv[4])  = br[1];
        *reinterpret_cast<float4*>(&Bv[8])  = br[2];
        *reinterpret_cast<float4*>(&Bv[12]) = br[3];
        *reinterpret_cast<float4*>(&Cv[0])  = br[4];
        *reinterpret_cast<float4*>(&Cv[4])  = br[5];
        *reinterpret_cast<float4*>(&Cv[8])  = br[6];
        *reinterpret_cast<float4*>(&Cv[12]) = br[7];
        float du = dtv * cv;
        float y0=0.f, y1=0.f, y2=0.f, y3=0.f;
        #pragma unroll
        for (int s=0;s<DST;s+=4){
            float dA0 = exp2f(dtv*A2[s+0]);
            float dA1 = exp2f(dtv*A2[s+1]);
            float dA2_ = exp2f(dtv*A2[s+2]);
            float dA3 = exp2f(dtv*A2[s+3]);
            h[s+0] = dA0*h[s+0] + du*Bv[s+0];
            h[s+1] = dA1*h[s+1] + du*Bv[s+1];
            h[s+2] = dA2_*h[s+2] + du*Bv[s+2];
            h[s+3] = dA3*h[s+3] + du*Bv[s+3];
            y0 += h[s+0]*Cv[s+0];
            y1 += h[s+1]*Cv[s+1];
            y2 += h[s+2]*Cv[s+2];
            y3 += h[s+3]*Cv[s+3];
        }
        float yv = (y0+y1)+(y2+y3) + cv*Dv;
        int zt = dir ? (NPATCH - t) : t;
        float zv = zp[(i64)zt*DX];
        yv *= siluf(zv);
        y[base + (i64)t*DI] = yv;
    }
}

// ---------------- combine -> ycb (bf16 split) ----------------
__global__ void combine_k(const float* __restrict__ y, __nv_bfloat16* __restrict__ ycb){
    i64 idx = (i64)blockIdx.x*256 + threadIdx.x;
    if (idx >= (i64)ROWS*DI) return;
    int d = (int)(idx % DI);
    i64 row = idx / DI;
    int b = (int)(row / LTOK); int t = (int)(row % LTOK);
    float a = y[idx];
    float bb = y[(i64)(ROWS + b*LTOK + (NPATCH - t))*DI + d];
    float o = 0.5f*(a + bb);
    __nv_bfloat16 hi = __float2bfloat16(o);
    ycb[row*(2*DI) + d]      = hi;
    ycb[row*(2*DI) + DI + d] = __float2bfloat16(o - __bfloat162float(hi));
}

// ---------------- final layer_norm(res[:,0] + h[:,0]) ----------------
__global__ void __launch_bounds__(256) final_k(
    const float* __restrict__ res, const float* __restrict__ h,
    const float* __restrict__ fw, const float* __restrict__ fb, float* __restrict__ out)
{
    int b = blockIdx.x; int tid = threadIdx.x;
    const float* rr = res + (i64)(b*LTOK)*DM;
    const float* hr = h + (i64)(b*LTOK)*DM;
    float v[3]; float s = 0.f;
    #pragma unroll
    for (int i=0;i<3;i++){ int d = tid + i*256; v[i] = rr[d] + hr[d]; s += v[i]; }
    __shared__ float red[256];
    red[tid] = s; __syncthreads();
    for (int st=128; st>0; st>>=1){ if (tid < st) red[tid] += red[tid+st]; __syncthreads(); }
    float mean = red[0] / (float)DM;
    __syncthreads();
    float q = 0.f;
    #pragma unroll
    for (int i=0;i<3;i++){ float t = v[i]-mean; q += t*t; }
    red[tid] = q; __syncthreads();
    for (int st=128; st>0; st>>=1){ if (tid < st) red[tid] += red[tid+st]; __syncthreads(); }
    float iv = rsqrtf(red[0]/(float)DM + 1e-5f);
    #pragma unroll
    for (int i=0;i<3;i++){ int d = tid + i*256; out[b*DM + d] = (v[i]-mean)*iv*fw[d] + fb[d]; }
}

// ---------------- host ----------------
#define STGB(TN) (2*128*80 + 2*(TN)*80)
#define EPIB(TN) (128*((TN)+4)*4)
#define SMEM128_ ((2*STGB(128)) > EPIB(128) ? (2*STGB(128)) : EPIB(128))
#define SMEM80_  ((2*STGB(80))  > EPIB(80)  ? (2*STGB(80))  : EPIB(80))

extern "C" void kernel_launch(void* const* d_in, const int* in_sizes, int n_in,
                              void* d_out, int out_size)
{
    const float* x       = (const float*)d_in[0];
    const float* patch_w = (const float*)d_in[1];
    const float* patch_b = (const float*)d_in[2];
    const float* cls     = (const float*)d_in[3];
    const float* pos     = (const float*)d_in[4];
    const float* ln_w    = (const float*)d_in[5];
    const float* w_in    = (const float*)d_in[6];
    const float* conv_w  = (const float*)d_in[7];
    const float* conv_b  = (const float*)d_in[8];
    const float* w_x     = (const float*)d_in[9];
    const float* w_dt    = (const float*)d_in[10];
    const float* b_dt    = (const float*)d_in[11];
    const float* a_log   = (const float*)d_in[12];
    const float* dd      = (const float*)d_in[13];
    const float* w_out   = (const float*)d_in[14];
    const float* fn_w    = (const float*)d_in[15];
    const float* fn_b    = (const float*)d_in[16];

    float *h,*res,*xz,*c,*dblb,*dtb,*y;
    __nv_bfloat16 *winb,*wxb,*wdtb,*woutb,*pwb,*xnb,*cb,*dtAb,*ycb,*xpb;
    cudaGetSymbolAddress((void**)&h,    g_h);
    cudaGetSymbolAddress((void**)&res,  g_res);
    cudaGetSymbolAddress((void**)&xz,   g_xz);
    cudaGetSymbolAddress((void**)&c,    g_c);
    cudaGetSymbolAddress((void**)&dblb, g_dbl);
    cudaGetSymbolAddress((void**)&dtb,  g_dt);
    cudaGetSymbolAddress((void**)&y,    g_y);
    cudaGetSymbolAddress((void**)&winb, g_winb);
    cudaGetSymbolAddress((void**)&wxb,  g_wxb);
    cudaGetSymbolAddress((void**)&wdtb, g_wdtb);
    cudaGetSymbolAddress((void**)&woutb,g_woutb);
    cudaGetSymbolAddress((void**)&pwb,  g_pwb);
    cudaGetSymbolAddress((void**)&xnb,  g_xnb);
    cudaGetSymbolAddress((void**)&cb,   g_cb);
    cudaGetSymbolAddress((void**)&dtAb, g_dtAb);
    cudaGetSymbolAddress((void**)&ycb,  g_ycb);
    cudaGetSymbolAddress((void**)&xpb,  g_xpb);

    cudaFuncSetAttribute((const void*)mma_gemm_k<128,0>, cudaFuncAttributeMaxDynamicSharedMemorySize, SMEM128_);
    cudaFuncSetAttribute((const void*)mma_gemm_k<128,1>, cudaFuncAttributeMaxDynamicSharedMemorySize, SMEM128_);
    cudaFuncSetAttribute((const void*)mma_gemm_k<128,2>, cudaFuncAttributeMaxDynamicSharedMemorySize, SMEM128_);
    cudaFuncSetAttribute((const void*)mma_gemm_k<80,3>,  cudaFuncAttributeMaxDynamicSharedMemorySize, SMEM80_);

    // launch 0: merged weight conversion
    wconv_all_k<<<(int)((WC_TOT + 255)/256), 256>>>(w_in, w_x, w_dt, w_out, patch_w,
                                                    winb, wxb, wdtb, woutb, pwb);
    // launches 1-3
    gather_xp_k<<<(BATCH*NPATCH*PKK + 255)/256, 256>>>(x, xpb);
    cls_fill_k<<<(BATCH*DM + 255)/256, 256>>>(cls, pos, h);
    mma_gemm_k<128,1><<<dim3(DM/128, (BATCH*NPATCH)/128, 1), 256, SMEM128_>>>(
        xpb, pwb, h, BATCH*NPATCH, PKK, DM, 0,0,0, patch_b, 0, pos, nullptr, 0);

    const int MT_ = (ROWS + 127)/128;  // 17
    for (int l=0; l<DEPTH; l++){
        addrms_k<<<ROWS, 256>>>(res, h, xnb, ln_w + (i64)l*DM, l==0 ? 1 : 0);

        // xz = xn @ w_in^T  (2052 x 3072 x 768)
        mma_gemm_k<128,0><<<dim3(DX/128, MT_, 1), 256, SMEM128_>>>(
            xnb, winb + (i64)l*DX*2*DM, xz, ROWS, DM, DX,
            0,0,0, nullptr, 0, nullptr, nullptr, 0);

        conv_k<<<dim3(DI/256, LTOK, BATCH*2), 256>>>(
            xz, conv_w + (i64)l*2*DI*4, conv_b + (i64)l*2*DI, c, cb);

        // dbl = c @ w_x^T  (2052 x 80 x 1536, 2 dirs) + dtA aux
        mma_gemm_k<80,3><<<dim3(1, MT_, 2), 256, SMEM80_>>>(
            cb, wxb + (i64)l*2*DBLN*2*DI, dblb, ROWS, DI, DBLN,
            (i64)ROWS*2*DI, (i64)DBLN*2*DI, (i64)ROWS*DBLN,
            nullptr, 0, nullptr, dtAb, (i64)ROWS*128);

        // dt = softplus(dtA @ w_dt^T + b_dt)  (2052 x 1536 x 48, 2 dirs)
        mma_gemm_k<128,2><<<dim3(DI/128, MT_, 2), 256, SMEM128_>>>(
            dtAb, wdtb + (i64)l*2*DI*128, dtb, ROWS, 64, DI,
            (i64)ROWS*128, (i64)DI*128, (i64)ROWS*DI,
            b_dt + (i64)l*2*DI, (i64)DI, nullptr, nullptr, 0);

        scan_k<<<dim3(DI/128, BATCH, 2), 128>>>(
            c, dtb, dblb, xz, a_log + (i64)l*2*DI*DST, dd + (i64)l*2*DI, y);

        combine_k<<<(int)(((i64)ROWS*DI + 255)/256), 256>>>(y, ycb);

        // h = yc @ w_out^T  (2052 x 768 x 1536)
        mma_gemm_k<128,0><<<dim3(DM/128, MT_, 1), 256, SMEM128_>>>(
            ycb, woutb + (i64)l*DM*2*DI, h, ROWS, DI, DM,
            0,0,0, nullptr, 0, nullptr, nullptr, 0);
    }

    final_k<<<BATCH, 256>>>(res, h, fn_w, fn_b, (float*)d_out);
}